// round 1
// baseline (speedup 1.0000x reference)
#include <cuda_runtime.h>
#include <math.h>

// Problem constants
#define NTOK 1024          // B*M tokens
#define DIM  1024          // D
#define HID  1024          // H
#define NE   16            // experts
#define NK   4             // top-k
#define NA   (NTOK*NK)     // 4096 assignments
#define NOUT 10
#define NB   64
#define NM   16

// Scratch (device globals: allocation-free)
__device__ __align__(16) float g_h[(size_t)NA*HID];   // 16 MB: relu(x@W1+b1) per assignment
__device__ __align__(16) float g_o[(size_t)NA*DIM];   // 16 MB: h@W2+b2 per assignment
__device__ int   g_tk_idx[NA];
__device__ float g_tk_gate[NA];
__device__ int   g_cnt[NE];
__device__ int   g_list[NE*NTOK];

__global__ void init_kernel() {
    if (threadIdx.x < NE) g_cnt[threadIdx.x] = 0;
}

// One block per token: logits = x_row @ w_gate, top-4, softmax, routing lists.
__global__ void gate_kernel(const float* __restrict__ x, const float* __restrict__ wg) {
    int n = blockIdx.x;
    int t = threadIdx.x;               // 256 threads
    float acc[16];
#pragma unroll
    for (int e = 0; e < 16; e++) acc[e] = 0.f;
    const float* xr = x + (size_t)n * DIM;
    for (int d = t; d < DIM; d += 256) {
        float xv = xr[d];
        const float4* w4 = (const float4*)(wg + (size_t)d * 16);
#pragma unroll
        for (int q = 0; q < 4; q++) {
            float4 w = w4[q];
            acc[q*4+0] = fmaf(xv, w.x, acc[q*4+0]);
            acc[q*4+1] = fmaf(xv, w.y, acc[q*4+1]);
            acc[q*4+2] = fmaf(xv, w.z, acc[q*4+2]);
            acc[q*4+3] = fmaf(xv, w.w, acc[q*4+3]);
        }
    }
#pragma unroll
    for (int e = 0; e < 16; e++)
        for (int off = 16; off; off >>= 1)
            acc[e] += __shfl_down_sync(0xffffffffu, acc[e], off);
    __shared__ float ws[8][16];
    int warp = t >> 5, lane = t & 31;
    if (lane == 0)
        for (int e = 0; e < 16; e++) ws[warp][e] = acc[e];
    __syncthreads();
    if (t == 0) {
        float l[16];
        for (int e = 0; e < 16; e++) {
            float s = 0.f;
            for (int w = 0; w < 8; w++) s += ws[w][e];
            l[e] = s;
        }
        int   idx[4];
        float val[4];
        for (int k = 0; k < 4; k++) {           // strict > : lowest index wins ties (matches top_k)
            float best = -INFINITY; int bi = 0;
            for (int e = 0; e < 16; e++) if (l[e] > best) { best = l[e]; bi = e; }
            idx[k] = bi; val[k] = best; l[bi] = -INFINITY;
        }
        float mx = val[0], s = 0.f, ex[4];
        for (int k = 0; k < 4; k++) { ex[k] = expf(val[k] - mx); s += ex[k]; }
        float inv = 1.f / s;
        for (int k = 0; k < 4; k++) {
            float g = ex[k] * inv;
            int a = n * 4 + k;
            g_tk_idx[a]  = idx[k];
            g_tk_gate[a] = g;
            int slot = atomicAdd(&g_cnt[idx[k]], 1);
            g_list[idx[k] * NTOK + slot] = a;   // list order irrelevant: per-assignment math
        }
    }
}

// Aux loss: importance/load per expert from tk arrays (deterministic order), cv^2.
__global__ void loss_kernel(float* __restrict__ d_out) {
    int t = threadIdx.x;                // 512 threads: warp w = expert w
    int w = t >> 5, lane = t & 31;
    float imp = 0.f, ld = 0.f;
    for (int a = lane; a < NA; a += 32) {
        if (g_tk_idx[a] == w) { imp += g_tk_gate[a]; ld += 1.f; }
    }
    for (int off = 16; off; off >>= 1) {
        imp += __shfl_down_sync(0xffffffffu, imp, off);
        ld  += __shfl_down_sync(0xffffffffu, ld,  off);
    }
    __shared__ float simp[16], sld[16];
    if (lane == 0) { simp[w] = imp; sld[w] = ld; }
    __syncthreads();
    if (t == 0) {
        float m1 = 0.f, m2 = 0.f;
        for (int e = 0; e < 16; e++) { m1 += simp[e]; m2 += sld[e]; }
        m1 *= (1.f/16.f); m2 *= (1.f/16.f);
        float v1 = 0.f, v2 = 0.f;
        for (int e = 0; e < 16; e++) {
            float a = simp[e] - m1, b = sld[e] - m2;
            v1 += a * a; v2 += b * b;
        }
        v1 *= (1.f/15.f); v2 *= (1.f/15.f);    // ddof=1
        float cv1 = v1 / (m1*m1 + 1e-10f);
        float cv2 = v2 / (m2*m2 + 1e-10f);
        d_out[640] = (cv1 + cv2) * 0.01f;
    }
}

// Gathered-row tiled GEMM, 64x64 tile, BK=16, 256 threads, 4x4 microtile.
// pass1: C=g_h, A=x (row = assignment>>2), +b1, relu.
// pass2: C=g_o, A=g_h (row = assignment),  +b2.
__global__ void expert_gemm(const float* __restrict__ x,
                            const float* __restrict__ W,
                            const float* __restrict__ bias,
                            int pass1) {
    int e   = blockIdx.z;
    int cnt = g_cnt[e];
    int m0  = blockIdx.y << 6;
    if (m0 >= cnt) return;
    int n0  = blockIdx.x << 6;

    const float* A_base = pass1 ? x : (const float*)g_h;
    float*       C      = pass1 ? g_h : g_o;
    const float* We     = W + (size_t)e * DIM * HID;

    __shared__ __align__(16) float As[16][68];
    __shared__ __align__(16) float Bs[16][68];
    __shared__ int rowid[64];

    int t = threadIdx.x;
    if (t < 64) {
        int mi = m0 + t;
        rowid[t] = (mi < cnt) ? g_list[e * NTOK + mi] : -1;
    }
    __syncthreads();

    int ty = t >> 4, tx = t & 15;
    int ar = t >> 2, aq = t & 3;         // A tile: 64 rows x 16 k, float4 along k
    int br = t >> 4, bc = (t & 15) << 2; // B tile: 16 k   x 64 n, float4 along n

    int aid_r = rowid[ar];
    int src = 0;
    if (aid_r >= 0) src = pass1 ? (aid_r >> 2) : aid_r;
    const float* Arow = A_base + (size_t)src * DIM + aq * 4;
    const float* Bptr = We + (size_t)br * HID + n0 + bc;

    float acc[4][4];
#pragma unroll
    for (int i = 0; i < 4; i++)
#pragma unroll
        for (int j = 0; j < 4; j++) acc[i][j] = 0.f;

    for (int k0 = 0; k0 < DIM; k0 += 16) {
        float4 av = *(const float4*)(Arow + k0);
        As[aq*4+0][ar] = av.x; As[aq*4+1][ar] = av.y;
        As[aq*4+2][ar] = av.z; As[aq*4+3][ar] = av.w;
        float4 bv = *(const float4*)(Bptr + (size_t)k0 * HID);
        *(float4*)&Bs[br][bc] = bv;
        __syncthreads();
#pragma unroll
        for (int kk = 0; kk < 16; kk++) {
            float4 a4 = *(const float4*)&As[kk][ty << 2];
            float4 b4 = *(const float4*)&Bs[kk][tx << 2];
            float a[4] = {a4.x, a4.y, a4.z, a4.w};
            float b[4] = {b4.x, b4.y, b4.z, b4.w};
#pragma unroll
            for (int i = 0; i < 4; i++)
#pragma unroll
                for (int j = 0; j < 4; j++)
                    acc[i][j] = fmaf(a[i], b[j], acc[i][j]);
        }
        __syncthreads();
    }

#pragma unroll
    for (int i = 0; i < 4; i++) {
        int mi  = (ty << 2) + i;
        int aid = rowid[mi];
        if (aid < 0) continue;
        int h = n0 + (tx << 2);
        float4 bz = *(const float4*)(bias + e * HID + h);
        float4 out;
        out.x = acc[i][0] + bz.x; out.y = acc[i][1] + bz.y;
        out.z = acc[i][2] + bz.z; out.w = acc[i][3] + bz.w;
        if (pass1) {
            out.x = fmaxf(out.x, 0.f); out.y = fmaxf(out.y, 0.f);
            out.z = fmaxf(out.z, 0.f); out.w = fmaxf(out.w, 0.f);
        }
        *(float4*)(C + (size_t)aid * HID + h) = out;
    }
}

__device__ float block_reduce_256(float v, volatile float* red) {
    int t = threadIdx.x;
    red[t] = v; __syncthreads();
    if (t < 128) red[t] += red[t + 128]; __syncthreads();
    if (t <  64) red[t] += red[t +  64]; __syncthreads();
    if (t <  32) {
        red[t] += red[t + 32]; __syncwarp();
        red[t] += red[t + 16]; __syncwarp();
        red[t] += red[t +  8]; __syncwarp();
        red[t] += red[t +  4]; __syncwarp();
        red[t] += red[t +  2]; __syncwarp();
        red[t] += red[t +  1]; __syncwarp();
    }
    __syncthreads();
    float r = red[0];
    __syncthreads();
    return r;
}

// Per batch row b: combine gated expert outputs, sum over M tokens, layernorm,
// scores = final @ W_los + b_los.
__global__ void finalize_kernel(const float* __restrict__ ln_w,
                                const float* __restrict__ ln_b,
                                const float* __restrict__ W_los,
                                const float* __restrict__ b_los,
                                float* __restrict__ d_out) {
    __shared__ float red[256];
    int b = blockIdx.x, t = threadIdx.x;
    float v[4];
#pragma unroll
    for (int i = 0; i < 4; i++) {
        int d = t + (i << 8);
        float acc = 0.f;
        for (int m = 0; m < NM; m++) {
            int n = (b << 4) + m;
#pragma unroll
            for (int k = 0; k < 4; k++) {
                int a = (n << 2) + k;
                acc = fmaf(g_tk_gate[a], g_o[(size_t)a * DIM + d], acc);
            }
        }
        v[i] = acc;
    }
    float s = 0.f, ss = 0.f;
#pragma unroll
    for (int i = 0; i < 4; i++) { s += v[i]; ss = fmaf(v[i], v[i], ss); }
    float sum   = block_reduce_256(s,  red);
    float sumsq = block_reduce_256(ss, red);
    float mu   = sum * (1.f / 1024.f);
    float var  = sumsq * (1.f / 1024.f) - mu * mu;
    float rstd = 1.f / sqrtf(var + 1e-5f);

    float sc[10];
#pragma unroll
    for (int o = 0; o < 10; o++) sc[o] = 0.f;
#pragma unroll
    for (int i = 0; i < 4; i++) {
        int d = t + (i << 8);
        float f = (v[i] - mu) * rstd * ln_w[d] + ln_b[d];
        const float* wl = W_los + (size_t)d * NOUT;
#pragma unroll
        for (int o = 0; o < 10; o++) sc[o] = fmaf(f, wl[o], sc[o]);
    }
    for (int o = 0; o < 10; o++) {
        float r = block_reduce_256(sc[o], red);
        if (t == 0) d_out[b * NOUT + o] = r + b_los[o];
    }
}

__global__ void predloss_kernel(const float* __restrict__ true_y, float* __restrict__ d_out) {
    __shared__ float red[256];
    int t = threadIdx.x;
    float s = 0.f;
    for (int i = t; i < NB * NOUT; i += 256) {
        float dd = d_out[i] - true_y[i];
        s = fmaf(dd, dd, s);
    }
    float r = block_reduce_256(s, red);
    if (t == 0) d_out[641] = r * (1.f / 640.f);
}

extern "C" void kernel_launch(void* const* d_in, const int* in_sizes, int n_in,
                              void* d_out, int out_size) {
    const float* x      = (const float*)d_in[0];   // mm_embed (B,M,D) -> (1024,1024)
    const float* wg     = (const float*)d_in[1];   // w_gate  (D,E)
    const float* W1     = (const float*)d_in[2];   // (E,D,H)
    const float* b1     = (const float*)d_in[3];   // (E,H)
    const float* W2     = (const float*)d_in[4];   // (E,H,D)
    const float* b2     = (const float*)d_in[5];   // (E,D)
    const float* ln_w   = (const float*)d_in[6];
    const float* ln_b   = (const float*)d_in[7];
    const float* W_los  = (const float*)d_in[8];   // (D,OUT)
    const float* b_los  = (const float*)d_in[9];
    const float* true_y = (const float*)d_in[10];  // (B,OUT)
    float* out = (float*)d_out;                    // [scores(640), loss, pred_loss]

    init_kernel<<<1, 32>>>();
    gate_kernel<<<NTOK, 256>>>(x, wg);
    loss_kernel<<<1, 512>>>(out);
    expert_gemm<<<dim3(16, 16, 16), 256>>>(x, W1, b1, 1);
    expert_gemm<<<dim3(16, 16, 16), 256>>>(x, W2, b2, 0);
    finalize_kernel<<<64, 256>>>(ln_w, ln_b, W_los, b_los, out);
    predloss_kernel<<<1, 256>>>(true_y, out);
}

// round 2
// speedup vs baseline: 1.1723x; 1.1723x over previous
#include <cuda_runtime.h>
#include <math.h>

// Problem constants
#define NTOK 1024          // B*M tokens
#define DIM  1024          // D
#define HID  1024          // H
#define NE   16            // experts
#define NK   4             // top-k
#define NA   (NTOK*NK)     // 4096 assignments
#define NOUT 10
#define NB   64
#define NM   16

// Scratch (device globals: allocation-free)
__device__ __align__(16) float g_h[(size_t)NA*HID];   // 16 MB: relu(x@W1+b1) per assignment
__device__ __align__(16) float g_o[(size_t)NA*DIM];   // 16 MB: h@W2+b2 per assignment
__device__ int   g_tk_idx[NA];
__device__ float g_tk_gate[NA];
__device__ int   g_cnt[NE];
__device__ int   g_list[NE*NTOK];

__global__ void init_kernel() {
    if (threadIdx.x < NE) g_cnt[threadIdx.x] = 0;
}

// One block per token: logits = x_row @ w_gate, top-4, softmax, routing lists.
__global__ void gate_kernel(const float* __restrict__ x, const float* __restrict__ wg) {
    int n = blockIdx.x;
    int t = threadIdx.x;               // 256 threads
    float acc[16];
#pragma unroll
    for (int e = 0; e < 16; e++) acc[e] = 0.f;
    const float* xr = x + (size_t)n * DIM;
    for (int d = t; d < DIM; d += 256) {
        float xv = xr[d];
        const float4* w4 = (const float4*)(wg + (size_t)d * 16);
#pragma unroll
        for (int q = 0; q < 4; q++) {
            float4 w = w4[q];
            acc[q*4+0] = fmaf(xv, w.x, acc[q*4+0]);
            acc[q*4+1] = fmaf(xv, w.y, acc[q*4+1]);
            acc[q*4+2] = fmaf(xv, w.z, acc[q*4+2]);
            acc[q*4+3] = fmaf(xv, w.w, acc[q*4+3]);
        }
    }
#pragma unroll
    for (int e = 0; e < 16; e++)
        for (int off = 16; off; off >>= 1)
            acc[e] += __shfl_down_sync(0xffffffffu, acc[e], off);
    __shared__ float ws[8][16];
    int warp = t >> 5, lane = t & 31;
    if (lane == 0)
        for (int e = 0; e < 16; e++) ws[warp][e] = acc[e];
    __syncthreads();
    if (t == 0) {
        float l[16];
        for (int e = 0; e < 16; e++) {
            float s = 0.f;
            for (int w = 0; w < 8; w++) s += ws[w][e];
            l[e] = s;
        }
        int   idx[4];
        float val[4];
        for (int k = 0; k < 4; k++) {           // strict > : lowest index wins ties (matches top_k)
            float best = -INFINITY; int bi = 0;
            for (int e = 0; e < 16; e++) if (l[e] > best) { best = l[e]; bi = e; }
            idx[k] = bi; val[k] = best; l[bi] = -INFINITY;
        }
        float mx = val[0], s = 0.f, ex[4];
        for (int k = 0; k < 4; k++) { ex[k] = expf(val[k] - mx); s += ex[k]; }
        float inv = 1.f / s;
        for (int k = 0; k < 4; k++) {
            float g = ex[k] * inv;
            int a = n * 4 + k;
            g_tk_idx[a]  = idx[k];
            g_tk_gate[a] = g;
            int slot = atomicAdd(&g_cnt[idx[k]], 1);
            g_list[idx[k] * NTOK + slot] = a;   // list order irrelevant: per-assignment math
        }
    }
}

// Aux loss: importance/load per expert from tk arrays (deterministic order), cv^2.
__global__ void loss_kernel(float* __restrict__ d_out) {
    int t = threadIdx.x;                // 512 threads: warp w = expert w
    int w = t >> 5, lane = t & 31;
    float imp = 0.f, ld = 0.f;
    for (int a = lane; a < NA; a += 32) {
        if (g_tk_idx[a] == w) { imp += g_tk_gate[a]; ld += 1.f; }
    }
    for (int off = 16; off; off >>= 1) {
        imp += __shfl_down_sync(0xffffffffu, imp, off);
        ld  += __shfl_down_sync(0xffffffffu, ld,  off);
    }
    __shared__ float simp[16], sld[16];
    if (lane == 0) { simp[w] = imp; sld[w] = ld; }
    __syncthreads();
    if (t == 0) {
        float m1 = 0.f, m2 = 0.f;
        for (int e = 0; e < 16; e++) { m1 += simp[e]; m2 += sld[e]; }
        m1 *= (1.f/16.f); m2 *= (1.f/16.f);
        float v1 = 0.f, v2 = 0.f;
        for (int e = 0; e < 16; e++) {
            float a = simp[e] - m1, b = sld[e] - m2;
            v1 += a * a; v2 += b * b;
        }
        v1 *= (1.f/15.f); v2 *= (1.f/15.f);    // ddof=1
        float cv1 = v1 / (m1*m1 + 1e-10f);
        float cv2 = v2 / (m2*m2 + 1e-10f);
        d_out[640] = (cv1 + cv2) * 0.01f;
    }
}

// Gathered-row tiled GEMM, 128x128 tile, BK=8, 256 threads, 8x8 microtile,
// double-buffered smem. 4 LDS.128 per 64 FMAs (2x the R1 ratio).
// pass1: C=g_h, A=x (row = assignment>>2), +b1, relu.
// pass2: C=g_o, A=g_h (row = assignment),  +b2.
__global__ void __launch_bounds__(256)
expert_gemm(const float* __restrict__ x,
            const float* __restrict__ W,
            const float* __restrict__ bias,
            int pass1) {
    int e   = blockIdx.z;
    int cnt = g_cnt[e];
    int m0  = blockIdx.y << 7;
    if (m0 >= cnt) return;
    int n0  = blockIdx.x << 7;

    const float* A_base = pass1 ? x : (const float*)g_h;
    float*       C      = pass1 ? g_h : g_o;
    const float* We     = W + (size_t)e * DIM * HID;

    __shared__ __align__(16) float As[2][8][132];   // A^T: [k][m], padded
    __shared__ __align__(16) float Bs[2][8][128];   // [k][n]
    __shared__ int rowid[128];

    int t = threadIdx.x;
    if (t < 128) {
        int mi = m0 + t;
        rowid[t] = (mi < cnt) ? g_list[e * NTOK + mi] : -1;
    }
    __syncthreads();

    // A staging: thread t loads float4 of row ar at k-offset aq
    int ar = t >> 1;               // 0..127
    int aq = (t & 1) << 2;         // 0 or 4
    int aid_r = rowid[ar];
    int src = 0;
    if (aid_r >= 0) src = pass1 ? (aid_r >> 2) : aid_r;
    const float* Arow = A_base + (size_t)src * DIM + aq;
    // B staging: thread t loads float4 of k-row br at n-offset bc
    int br = t >> 5;               // 0..7
    int bc = (t & 31) << 2;        // 0..124
    const float* Bptr = We + (size_t)br * HID + n0 + bc;

    int ty = t >> 4;               // 0..15 -> m = ty*8
    int tx = t & 15;               // 0..15 -> n = tx*8

    float acc[8][8];
#pragma unroll
    for (int i = 0; i < 8; i++)
#pragma unroll
        for (int j = 0; j < 8; j++) acc[i][j] = 0.f;

    // Preload tile 0
    {
        float4 av = *(const float4*)(Arow);
        As[0][aq+0][ar] = av.x; As[0][aq+1][ar] = av.y;
        As[0][aq+2][ar] = av.z; As[0][aq+3][ar] = av.w;
        *(float4*)&Bs[0][br][bc] = *(const float4*)(Bptr);
    }
    __syncthreads();

    int cur = 0;
    for (int kt = 1; kt <= DIM/8; kt++) {
        float4 av, bv;
        bool more = (kt < DIM/8);
        if (more) {
            av = *(const float4*)(Arow + kt*8);
            bv = *(const float4*)(Bptr + (size_t)(kt*8) * HID);
        }
#pragma unroll
        for (int kk = 0; kk < 8; kk++) {
            float4 a0 = *(const float4*)&As[cur][kk][ty<<3];
            float4 a1 = *(const float4*)&As[cur][kk][(ty<<3)+4];
            float4 b0 = *(const float4*)&Bs[cur][kk][tx<<3];
            float4 b1 = *(const float4*)&Bs[cur][kk][(tx<<3)+4];
            float a[8] = {a0.x,a0.y,a0.z,a0.w,a1.x,a1.y,a1.z,a1.w};
            float b[8] = {b0.x,b0.y,b0.z,b0.w,b1.x,b1.y,b1.z,b1.w};
#pragma unroll
            for (int i = 0; i < 8; i++)
#pragma unroll
                for (int j = 0; j < 8; j++)
                    acc[i][j] = fmaf(a[i], b[j], acc[i][j]);
        }
        if (more) {
            int nxt = cur ^ 1;
            As[nxt][aq+0][ar] = av.x; As[nxt][aq+1][ar] = av.y;
            As[nxt][aq+2][ar] = av.z; As[nxt][aq+3][ar] = av.w;
            *(float4*)&Bs[nxt][br][bc] = bv;
            __syncthreads();
            cur = nxt;
        }
    }

    // Epilogue: bias (+relu for pass1), gathered-row stores
    int n = n0 + (tx << 3);
    float4 bz0 = *(const float4*)(bias + e * HID + n);
    float4 bz1 = *(const float4*)(bias + e * HID + n + 4);
#pragma unroll
    for (int i = 0; i < 8; i++) {
        int mi  = (ty << 3) + i;
        int aid = rowid[mi];
        if (aid < 0) continue;
        float4 o0, o1;
        o0.x = acc[i][0] + bz0.x; o0.y = acc[i][1] + bz0.y;
        o0.z = acc[i][2] + bz0.z; o0.w = acc[i][3] + bz0.w;
        o1.x = acc[i][4] + bz1.x; o1.y = acc[i][5] + bz1.y;
        o1.z = acc[i][6] + bz1.z; o1.w = acc[i][7] + bz1.w;
        if (pass1) {
            o0.x = fmaxf(o0.x, 0.f); o0.y = fmaxf(o0.y, 0.f);
            o0.z = fmaxf(o0.z, 0.f); o0.w = fmaxf(o0.w, 0.f);
            o1.x = fmaxf(o1.x, 0.f); o1.y = fmaxf(o1.y, 0.f);
            o1.z = fmaxf(o1.z, 0.f); o1.w = fmaxf(o1.w, 0.f);
        }
        float* Crow = C + (size_t)aid * HID + n;
        *(float4*)(Crow)     = o0;
        *(float4*)(Crow + 4) = o1;
    }
}

__device__ float block_reduce_256(float v, volatile float* red) {
    int t = threadIdx.x;
    red[t] = v; __syncthreads();
    if (t < 128) red[t] += red[t + 128]; __syncthreads();
    if (t <  64) red[t] += red[t +  64]; __syncthreads();
    if (t <  32) {
        red[t] += red[t + 32]; __syncwarp();
        red[t] += red[t + 16]; __syncwarp();
        red[t] += red[t +  8]; __syncwarp();
        red[t] += red[t +  4]; __syncwarp();
        red[t] += red[t +  2]; __syncwarp();
        red[t] += red[t +  1]; __syncwarp();
    }
    __syncthreads();
    float r = red[0];
    __syncthreads();
    return r;
}

// Per batch row b: combine gated expert outputs, sum over M tokens, layernorm,
// scores = final @ W_los + b_los.
__global__ void finalize_kernel(const float* __restrict__ ln_w,
                                const float* __restrict__ ln_b,
                                const float* __restrict__ W_los,
                                const float* __restrict__ b_los,
                                float* __restrict__ d_out) {
    __shared__ float red[256];
    int b = blockIdx.x, t = threadIdx.x;
    float v[4];
#pragma unroll
    for (int i = 0; i < 4; i++) {
        int d = t + (i << 8);
        float acc = 0.f;
        for (int m = 0; m < NM; m++) {
            int n = (b << 4) + m;
#pragma unroll
            for (int k = 0; k < 4; k++) {
                int a = (n << 2) + k;
                acc = fmaf(g_tk_gate[a], g_o[(size_t)a * DIM + d], acc);
            }
        }
        v[i] = acc;
    }
    float s = 0.f, ss = 0.f;
#pragma unroll
    for (int i = 0; i < 4; i++) { s += v[i]; ss = fmaf(v[i], v[i], ss); }
    float sum   = block_reduce_256(s,  red);
    float sumsq = block_reduce_256(ss, red);
    float mu   = sum * (1.f / 1024.f);
    float var  = sumsq * (1.f / 1024.f) - mu * mu;
    float rstd = 1.f / sqrtf(var + 1e-5f);

    float sc[10];
#pragma unroll
    for (int o = 0; o < 10; o++) sc[o] = 0.f;
#pragma unroll
    for (int i = 0; i < 4; i++) {
        int d = t + (i << 8);
        float f = (v[i] - mu) * rstd * ln_w[d] + ln_b[d];
        const float* wl = W_los + (size_t)d * NOUT;
#pragma unroll
        for (int o = 0; o < 10; o++) sc[o] = fmaf(f, wl[o], sc[o]);
    }
    for (int o = 0; o < 10; o++) {
        float r = block_reduce_256(sc[o], red);
        if (t == 0) d_out[b * NOUT + o] = r + b_los[o];
    }
}

__global__ void predloss_kernel(const float* __restrict__ true_y, float* __restrict__ d_out) {
    __shared__ float red[256];
    int t = threadIdx.x;
    float s = 0.f;
    for (int i = t; i < NB * NOUT; i += 256) {
        float dd = d_out[i] - true_y[i];
        s = fmaf(dd, dd, s);
    }
    float r = block_reduce_256(s, red);
    if (t == 0) d_out[641] = r * (1.f / 640.f);
}

extern "C" void kernel_launch(void* const* d_in, const int* in_sizes, int n_in,
                              void* d_out, int out_size) {
    const float* x      = (const float*)d_in[0];   // mm_embed (B,M,D) -> (1024,1024)
    const float* wg     = (const float*)d_in[1];   // w_gate  (D,E)
    const float* W1     = (const float*)d_in[2];   // (E,D,H)
    const float* b1     = (const float*)d_in[3];   // (E,H)
    const float* W2     = (const float*)d_in[4];   // (E,H,D)
    const float* b2     = (const float*)d_in[5];   // (E,D)
    const float* ln_w   = (const float*)d_in[6];
    const float* ln_b   = (const float*)d_in[7];
    const float* W_los  = (const float*)d_in[8];   // (D,OUT)
    const float* b_los  = (const float*)d_in[9];
    const float* true_y = (const float*)d_in[10];  // (B,OUT)
    float* out = (float*)d_out;                    // [scores(640), loss, pred_loss]

    init_kernel<<<1, 32>>>();
    gate_kernel<<<NTOK, 256>>>(x, wg);
    loss_kernel<<<1, 512>>>(out);
    expert_gemm<<<dim3(8, 8, 16), 256>>>(x, W1, b1, 1);
    expert_gemm<<<dim3(8, 8, 16), 256>>>(x, W2, b2, 0);
    finalize_kernel<<<64, 256>>>(ln_w, ln_b, W_los, b_los, out);
    predloss_kernel<<<1, 256>>>(true_y, out);
}

// round 4
// speedup vs baseline: 1.2578x; 1.0729x over previous
#include <cuda_runtime.h>
#include <cuda_bf16.h>
#include <math.h>
#include <stdint.h>

// Problem constants
#define NTOK 1024
#define DIM  1024
#define HID  1024
#define NE   16
#define NK   4
#define NA   (NTOK*NK)
#define NOUT 10
#define NB   64
#define NM   16

// Scratch (device globals: allocation-free)
__device__ __align__(16) float g_h[(size_t)NA*HID];
__device__ __align__(16) float g_o[(size_t)NA*DIM];
__device__ int   g_tk_idx[NA];
__device__ float g_tk_gate[NA];
__device__ int   g_cnt[NE];
__device__ int   g_list[NE*NTOK];

__device__ __forceinline__ uint32_t smem_u32(const void* p) {
    uint32_t a;
    asm("{ .reg .u64 t; cvta.to.shared.u64 t, %1; cvt.u32.u64 %0, t; }" : "=r"(a) : "l"(p));
    return a;
}
__device__ __forceinline__ void ldsm4(uint32_t& r0, uint32_t& r1, uint32_t& r2, uint32_t& r3, uint32_t a) {
    asm volatile("ldmatrix.sync.aligned.m8n8.x4.shared.b16 {%0,%1,%2,%3}, [%4];"
                 : "=r"(r0), "=r"(r1), "=r"(r2), "=r"(r3) : "r"(a));
}
__device__ __forceinline__ void ldsm4t(uint32_t& r0, uint32_t& r1, uint32_t& r2, uint32_t& r3, uint32_t a) {
    asm volatile("ldmatrix.sync.aligned.m8n8.x4.trans.shared.b16 {%0,%1,%2,%3}, [%4];"
                 : "=r"(r0), "=r"(r1), "=r"(r2), "=r"(r3) : "r"(a));
}
__device__ __forceinline__ void mma16816(float* c, const uint32_t* a, uint32_t b0, uint32_t b1) {
    asm volatile("mma.sync.aligned.m16n8k16.row.col.f32.bf16.bf16.f32 "
                 "{%0,%1,%2,%3}, {%4,%5,%6,%7}, {%8,%9}, {%0,%1,%2,%3};"
                 : "+f"(c[0]), "+f"(c[1]), "+f"(c[2]), "+f"(c[3])
                 : "r"(a[0]), "r"(a[1]), "r"(a[2]), "r"(a[3]), "r"(b0), "r"(b1));
}

// XOR swizzle inside 128B rows (16B granules)
#define SWZ(row, cb) ((row)*128 + ((cb) ^ (((row)&7)<<4)))

__global__ void init_kernel() {
    if (threadIdx.x < NE) g_cnt[threadIdx.x] = 0;
}

// One block per token: logits = x_row @ w_gate, top-4, softmax, routing lists.
__global__ void gate_kernel(const float* __restrict__ x, const float* __restrict__ wg) {
    int n = blockIdx.x;
    int t = threadIdx.x;               // 256 threads
    float acc[16];
#pragma unroll
    for (int e = 0; e < 16; e++) acc[e] = 0.f;
    const float* xr = x + (size_t)n * DIM;
    for (int d = t; d < DIM; d += 256) {
        float xv = xr[d];
        const float4* w4 = (const float4*)(wg + (size_t)d * 16);
#pragma unroll
        for (int q = 0; q < 4; q++) {
            float4 w = w4[q];
            acc[q*4+0] = fmaf(xv, w.x, acc[q*4+0]);
            acc[q*4+1] = fmaf(xv, w.y, acc[q*4+1]);
            acc[q*4+2] = fmaf(xv, w.z, acc[q*4+2]);
            acc[q*4+3] = fmaf(xv, w.w, acc[q*4+3]);
        }
    }
#pragma unroll
    for (int e = 0; e < 16; e++)
        for (int off = 16; off; off >>= 1)
            acc[e] += __shfl_down_sync(0xffffffffu, acc[e], off);
    __shared__ float ws[8][16];
    int warp = t >> 5, lane = t & 31;
    if (lane == 0)
        for (int e = 0; e < 16; e++) ws[warp][e] = acc[e];
    __syncthreads();
    if (t == 0) {
        float l[16];
        for (int e = 0; e < 16; e++) {
            float s = 0.f;
            for (int w = 0; w < 8; w++) s += ws[w][e];
            l[e] = s;
        }
        int   idx[4];
        float val[4];
        for (int k = 0; k < 4; k++) {
            float best = -INFINITY; int bi = 0;
            for (int e = 0; e < 16; e++) if (l[e] > best) { best = l[e]; bi = e; }
            idx[k] = bi; val[k] = best; l[bi] = -INFINITY;
        }
        float mx = val[0], s = 0.f, ex[4];
        for (int k = 0; k < 4; k++) { ex[k] = expf(val[k] - mx); s += ex[k]; }
        float inv = 1.f / s;
        for (int k = 0; k < 4; k++) {
            float g = ex[k] * inv;
            int a = n * 4 + k;
            g_tk_idx[a]  = idx[k];
            g_tk_gate[a] = g;
            int slot = atomicAdd(&g_cnt[idx[k]], 1);
            g_list[idx[k] * NTOK + slot] = a;
        }
    }
}

// Aux loss
__global__ void loss_kernel(float* __restrict__ d_out) {
    int t = threadIdx.x;
    int w = t >> 5, lane = t & 31;
    float imp = 0.f, ld = 0.f;
    for (int a = lane; a < NA; a += 32) {
        if (g_tk_idx[a] == w) { imp += g_tk_gate[a]; ld += 1.f; }
    }
    for (int off = 16; off; off >>= 1) {
        imp += __shfl_down_sync(0xffffffffu, imp, off);
        ld  += __shfl_down_sync(0xffffffffu, ld,  off);
    }
    __shared__ float simp[16], sld[16];
    if (lane == 0) { simp[w] = imp; sld[w] = ld; }
    __syncthreads();
    if (t == 0) {
        float m1 = 0.f, m2 = 0.f;
        for (int e = 0; e < 16; e++) { m1 += simp[e]; m2 += sld[e]; }
        m1 *= (1.f/16.f); m2 *= (1.f/16.f);
        float v1 = 0.f, v2 = 0.f;
        for (int e = 0; e < 16; e++) {
            float a = simp[e] - m1, b = sld[e] - m2;
            v1 += a * a; v2 += b * b;
        }
        v1 *= (1.f/15.f); v2 *= (1.f/15.f);
        float cv1 = v1 / (m1*m1 + 1e-10f);
        float cv2 = v2 / (m2*m2 + 1e-10f);
        d_out[640] = (cv1 + cv2) * 0.01f;
    }
}

// HMMA bf16 3-split gathered expert GEMM. CTA tile 128(M) x 64(N), KC=64.
// 8 warps: warp (wm = wid&3, wn = wid>>2) computes 32x32.
// pass1: A=x (row aid>>2) -> g_h (+b1, relu). pass2: A=g_h (row aid) -> g_o (+b2).
__global__ void __launch_bounds__(256)
expert_gemm_mma(const float* __restrict__ x,
                const float* __restrict__ W,
                const float* __restrict__ bias,
                int pass1) {
    int e   = blockIdx.z;
    int cnt = g_cnt[e];
    int m0  = blockIdx.y << 7;
    if (m0 >= cnt) return;
    int n0  = blockIdx.x << 6;

    __shared__ __align__(16) uint8_t Ahi[128*128];
    __shared__ __align__(16) uint8_t Alo[128*128];
    __shared__ __align__(16) uint8_t Bhi[64*128];
    __shared__ __align__(16) uint8_t Blo[64*128];

    const float* A_base = pass1 ? x : (const float*)g_h;
    float*       C      = pass1 ? g_h : g_o;
    const float* We     = W + (size_t)e * DIM * HID;

    int t = threadIdx.x, wid = t >> 5, lane = t & 31;

    // A staging role: row = t>>1 (128 rows), half = t&1 (32 elems each)
    int arow = t >> 1, ahalf = t & 1;
    int mi_s = m0 + arow;
    int aid_s = (mi_s < cnt) ? g_list[e * NTOK + mi_s] : -1;
    int asrc = 0;
    if (aid_s >= 0) asrc = pass1 ? (aid_s >> 2) : aid_s;
    const float* Arow = A_base + (size_t)asrc * DIM + ahalf * 32;
    // B staging role: krow = t>>2 (64 rows), quarter = t&3 (16 n-elems each)
    int bkr = t >> 2, bq = t & 3;
    const float* Bptr = We + (size_t)bkr * HID + n0 + bq * 16;

    uint32_t aHiB = smem_u32(Ahi), aLoB = smem_u32(Alo);
    uint32_t bHiB = smem_u32(Bhi), bLoB = smem_u32(Blo);

    int wm = wid & 3, wn = wid >> 2;

    float acc[2][4][4];
#pragma unroll
    for (int i = 0; i < 2; i++)
#pragma unroll
        for (int j = 0; j < 4; j++)
#pragma unroll
            for (int q = 0; q < 4; q++) acc[i][j][q] = 0.f;

    // fragment smem addresses (constant across chunks except ks offset)
    uint32_t aAddr[2], bAddr[2];
#pragma unroll
    for (int i = 0; i < 2; i++) {
        int r = wm * 32 + i * 16 + (lane & 15);
        int cb = (lane >> 4) << 4;
        aAddr[i] = (uint32_t)SWZ(r, cb);
    }
#pragma unroll
    for (int jp = 0; jp < 2; jp++) {
        int r = lane & 15;
        int cb = wn * 64 + jp * 32 + ((lane >> 4) << 4);
        bAddr[jp] = (uint32_t)SWZ(r, cb);
    }

    for (int c = 0; c < DIM / 64; c++) {
        int k0 = c * 64;
        // preload into regs
        float4 fa[8], fb[4];
        const float4* ap = (const float4*)(Arow + k0);
#pragma unroll
        for (int q = 0; q < 8; q++) fa[q] = ap[q];
        const float4* bp = (const float4*)(Bptr + (size_t)k0 * HID);
#pragma unroll
        for (int q = 0; q < 4; q++) fb[q] = bp[q];

        __syncthreads();   // previous chunk's compute done

        // A: 32 elems -> 4 x 16B hi + lo
#pragma unroll
        for (int q = 0; q < 4; q++) {
            float4 u = fa[2*q], v = fa[2*q+1];
            float pv[8] = {u.x,u.y,u.z,u.w,v.x,v.y,v.z,v.w};
            uint32_t hi[4], lo[4];
#pragma unroll
            for (int p = 0; p < 4; p++) {
                __nv_bfloat162 h2 = __floats2bfloat162_rn(pv[2*p], pv[2*p+1]);
                float2 hf = __bfloat1622float2(h2);
                __nv_bfloat162 l2 = __floats2bfloat162_rn(pv[2*p] - hf.x, pv[2*p+1] - hf.y);
                hi[p] = *(uint32_t*)&h2;
                lo[p] = *(uint32_t*)&l2;
            }
            int off = SWZ(arow, ahalf*64 + q*16);
            *(uint4*)(Ahi + off) = make_uint4(hi[0],hi[1],hi[2],hi[3]);
            *(uint4*)(Alo + off) = make_uint4(lo[0],lo[1],lo[2],lo[3]);
        }
        // B: 16 elems -> 2 x 16B hi + lo
#pragma unroll
        for (int h = 0; h < 2; h++) {
            float4 u = fb[2*h], v = fb[2*h+1];
            float pv[8] = {u.x,u.y,u.z,u.w,v.x,v.y,v.z,v.w};
            uint32_t hi[4], lo[4];
#pragma unroll
            for (int p = 0; p < 4; p++) {
                __nv_bfloat162 h2 = __floats2bfloat162_rn(pv[2*p], pv[2*p+1]);
                float2 hf = __bfloat1622float2(h2);
                __nv_bfloat162 l2 = __floats2bfloat162_rn(pv[2*p] - hf.x, pv[2*p+1] - hf.y);
                hi[p] = *(uint32_t*)&h2;
                lo[p] = *(uint32_t*)&l2;
            }
            int off = SWZ(bkr, bq*32 + h*16);
            *(uint4*)(Bhi + off) = make_uint4(hi[0],hi[1],hi[2],hi[3]);
            *(uint4*)(Blo + off) = make_uint4(lo[0],lo[1],lo[2],lo[3]);
        }
        __syncthreads();

        // compute 4 k16 steps
#pragma unroll
        for (int ks = 0; ks < 4; ks++) {
            uint32_t ksa = (uint32_t)(ks * 32);
            // ks offset lives in swizzled low bits region? cb bits 5-6 not in XOR mask (mask 0x70 covers bits 4-6).
            // SWZ xors bits 4-6; ks*32 touches bits 5-6 -> must re-swizzle, so add ks offset pre-swizzle:
            uint32_t ah[2][4], al[2][4];
#pragma unroll
            for (int i = 0; i < 2; i++) {
                int r = wm * 32 + i * 16 + (lane & 15);
                int cb = ks*32 + ((lane >> 4) << 4);
                uint32_t ad = (uint32_t)SWZ(r, cb);
                ldsm4(ah[i][0], ah[i][1], ah[i][2], ah[i][3], aHiB + ad);
                ldsm4(al[i][0], al[i][1], al[i][2], al[i][3], aLoB + ad);
            }
            uint32_t bh[4][2], bl[4][2];
#pragma unroll
            for (int jp = 0; jp < 2; jp++) {
                int r = ks * 16 + (lane & 15);
                int cb = wn * 64 + jp * 32 + ((lane >> 4) << 4);
                uint32_t bd = (uint32_t)SWZ(r, cb);
                uint32_t r0,r1,r2,r3;
                ldsm4t(r0, r1, r2, r3, bHiB + bd);
                bh[jp*2][0]=r0; bh[jp*2][1]=r1; bh[jp*2+1][0]=r2; bh[jp*2+1][1]=r3;
                ldsm4t(r0, r1, r2, r3, bLoB + bd);
                bl[jp*2][0]=r0; bl[jp*2][1]=r1; bl[jp*2+1][0]=r2; bl[jp*2+1][1]=r3;
            }
            (void)ksa;
#pragma unroll
            for (int i = 0; i < 2; i++)
#pragma unroll
                for (int j = 0; j < 4; j++) {
                    mma16816(acc[i][j], ah[i], bh[j][0], bh[j][1]);
                    mma16816(acc[i][j], ah[i], bl[j][0], bl[j][1]);
                    mma16816(acc[i][j], al[i], bh[j][0], bh[j][1]);
                }
        }
    }

    // Epilogue: scatter-store with bias (+relu pass1)
    int colb = n0 + wn * 32 + (lane & 3) * 2;
    float2 bz[4];
#pragma unroll
    for (int j = 0; j < 4; j++)
        bz[j] = *(const float2*)(bias + e * HID + colb + j * 8);

#pragma unroll
    for (int i = 0; i < 2; i++) {
#pragma unroll
        for (int rh = 0; rh < 2; rh++) {
            int row = wm * 32 + i * 16 + rh * 8 + (lane >> 2);
            int mi = m0 + row;
            int aid = (mi < cnt) ? g_list[e * NTOK + mi] : -1;
            if (aid < 0) continue;
            float* Crow = C + (size_t)aid * HID;
#pragma unroll
            for (int j = 0; j < 4; j++) {
                float2 o;
                o.x = acc[i][j][rh*2+0] + bz[j].x;
                o.y = acc[i][j][rh*2+1] + bz[j].y;
                if (pass1) { o.x = fmaxf(o.x, 0.f); o.y = fmaxf(o.y, 0.f); }
                *(float2*)(Crow + colb + j * 8) = o;
            }
        }
    }
}

__device__ float block_reduce_256(float v, volatile float* red) {
    int t = threadIdx.x;
    red[t] = v; __syncthreads();
    if (t < 128) red[t] += red[t + 128]; __syncthreads();
    if (t <  64) red[t] += red[t +  64]; __syncthreads();
    if (t <  32) {
        red[t] += red[t + 32]; __syncwarp();
        red[t] += red[t + 16]; __syncwarp();
        red[t] += red[t +  8]; __syncwarp();
        red[t] += red[t +  4]; __syncwarp();
        red[t] += red[t +  2]; __syncwarp();
        red[t] += red[t +  1]; __syncwarp();
    }
    __syncthreads();
    float r = red[0];
    __syncthreads();
    return r;
}

__global__ void finalize_kernel(const float* __restrict__ ln_w,
                                const float* __restrict__ ln_b,
                                const float* __restrict__ W_los,
                                const float* __restrict__ b_los,
                                float* __restrict__ d_out) {
    __shared__ float red[256];
    int b = blockIdx.x, t = threadIdx.x;
    float v[4];
#pragma unroll
    for (int i = 0; i < 4; i++) {
        int d = t + (i << 8);
        float acc = 0.f;
        for (int m = 0; m < NM; m++) {
            int n = (b << 4) + m;
#pragma unroll
            for (int k = 0; k < 4; k++) {
                int a = (n << 2) + k;
                acc = fmaf(g_tk_gate[a], g_o[(size_t)a * DIM + d], acc);
            }
        }
        v[i] = acc;
    }
    float s = 0.f, ss = 0.f;
#pragma unroll
    for (int i = 0; i < 4; i++) { s += v[i]; ss = fmaf(v[i], v[i], ss); }
    float sum   = block_reduce_256(s,  red);
    float sumsq = block_reduce_256(ss, red);
    float mu   = sum * (1.f / 1024.f);
    float var  = sumsq * (1.f / 1024.f) - mu * mu;
    float rstd = 1.f / sqrtf(var + 1e-5f);

    float sc[10];
#pragma unroll
    for (int o = 0; o < 10; o++) sc[o] = 0.f;
#pragma unroll
    for (int i = 0; i < 4; i++) {
        int d = t + (i << 8);
        float f = (v[i] - mu) * rstd * ln_w[d] + ln_b[d];
        const float* wl = W_los + (size_t)d * NOUT;
#pragma unroll
        for (int o = 0; o < 10; o++) sc[o] = fmaf(f, wl[o], sc[o]);
    }
    for (int o = 0; o < 10; o++) {
        float r = block_reduce_256(sc[o], red);
        if (t == 0) d_out[b * NOUT + o] = r + b_los[o];
    }
}

__global__ void predloss_kernel(const float* __restrict__ true_y, float* __restrict__ d_out) {
    __shared__ float red[256];
    int t = threadIdx.x;
    float s = 0.f;
    for (int i = t; i < NB * NOUT; i += 256) {
        float dd = d_out[i] - true_y[i];
        s = fmaf(dd, dd, s);
    }
    float r = block_reduce_256(s, red);
    if (t == 0) d_out[641] = r * (1.f / 640.f);
}

extern "C" void kernel_launch(void* const* d_in, const int* in_sizes, int n_in,
                              void* d_out, int out_size) {
    const float* x      = (const float*)d_in[0];
    const float* wg     = (const float*)d_in[1];
    const float* W1     = (const float*)d_in[2];
    const float* b1     = (const float*)d_in[3];
    const float* W2     = (const float*)d_in[4];
    const float* b2     = (const float*)d_in[5];
    const float* ln_w   = (const float*)d_in[6];
    const float* ln_b   = (const float*)d_in[7];
    const float* W_los  = (const float*)d_in[8];
    const float* b_los  = (const float*)d_in[9];
    const float* true_y = (const float*)d_in[10];
    float* out = (float*)d_out;

    init_kernel<<<1, 32>>>();
    gate_kernel<<<NTOK, 256>>>(x, wg);
    loss_kernel<<<1, 512>>>(out);
    expert_gemm_mma<<<dim3(16, 8, 16), 256>>>(x, W1, b1, 1);
    expert_gemm_mma<<<dim3(16, 8, 16), 256>>>(x, W2, b2, 0);
    finalize_kernel<<<64, 256>>>(ln_w, ln_b, W_los, b_los, out);
    predloss_kernel<<<1, 256>>>(true_y, out);
}

// round 5
// speedup vs baseline: 1.6739x; 1.3309x over previous
#include <cuda_runtime.h>
#include <cuda_bf16.h>
#include <math.h>
#include <stdint.h>

// Problem constants
#define NTOK 1024
#define DIM  1024
#define HID  1024
#define NE   16
#define NK   4
#define NA   (NTOK*NK)
#define NOUT 10
#define NB   64
#define NM   16

// Scratch (device globals: allocation-free)
__device__ __align__(16) float g_h[(size_t)NA*HID];
__device__ __align__(16) float g_o[(size_t)NA*DIM];
__device__ int   g_tk_idx[NA];
__device__ float g_tk_gate[NA];
__device__ int   g_cnt[NE];
__device__ int   g_list[NE*NTOK];

__device__ __forceinline__ uint32_t smem_u32(const void* p) {
    uint32_t a;
    asm("{ .reg .u64 t; cvta.to.shared.u64 t, %1; cvt.u32.u64 %0, t; }" : "=r"(a) : "l"(p));
    return a;
}
__device__ __forceinline__ void ldsm4(uint32_t& r0, uint32_t& r1, uint32_t& r2, uint32_t& r3, uint32_t a) {
    asm volatile("ldmatrix.sync.aligned.m8n8.x4.shared.b16 {%0,%1,%2,%3}, [%4];"
                 : "=r"(r0), "=r"(r1), "=r"(r2), "=r"(r3) : "r"(a));
}
__device__ __forceinline__ void ldsm4t(uint32_t& r0, uint32_t& r1, uint32_t& r2, uint32_t& r3, uint32_t a) {
    asm volatile("ldmatrix.sync.aligned.m8n8.x4.trans.shared.b16 {%0,%1,%2,%3}, [%4];"
                 : "=r"(r0), "=r"(r1), "=r"(r2), "=r"(r3) : "r"(a));
}
__device__ __forceinline__ void mma16816(float* c, const uint32_t* a, uint32_t b0, uint32_t b1) {
    asm volatile("mma.sync.aligned.m16n8k16.row.col.f32.bf16.bf16.f32 "
                 "{%0,%1,%2,%3}, {%4,%5,%6,%7}, {%8,%9}, {%0,%1,%2,%3};"
                 : "+f"(c[0]), "+f"(c[1]), "+f"(c[2]), "+f"(c[3])
                 : "r"(a[0]), "r"(a[1]), "r"(a[2]), "r"(a[3]), "r"(b0), "r"(b1));
}

// XOR swizzle inside 128B rows (16B granules)
#define SWZ(row, cb) ((row)*128 + ((cb) ^ (((row)&7)<<4)))

// per-stage smem layout (bytes)
#define S_AHI 0
#define S_ALO (128*128)
#define S_BHI (2*128*128)
#define S_BLO (2*128*128 + 64*128)
#define STAGE_BYTES (2*128*128 + 2*64*128)     // 48KB
#define SMEM_TOTAL  (2*STAGE_BYTES)            // 96KB

__global__ void init_kernel() {
    if (threadIdx.x < NE) g_cnt[threadIdx.x] = 0;
}

// One block per token: logits = x_row @ w_gate, top-4, softmax, routing lists.
__global__ void gate_kernel(const float* __restrict__ x, const float* __restrict__ wg) {
    int n = blockIdx.x;
    int t = threadIdx.x;               // 256 threads
    float acc[16];
#pragma unroll
    for (int e = 0; e < 16; e++) acc[e] = 0.f;
    const float* xr = x + (size_t)n * DIM;
    for (int d = t; d < DIM; d += 256) {
        float xv = xr[d];
        const float4* w4 = (const float4*)(wg + (size_t)d * 16);
#pragma unroll
        for (int q = 0; q < 4; q++) {
            float4 w = w4[q];
            acc[q*4+0] = fmaf(xv, w.x, acc[q*4+0]);
            acc[q*4+1] = fmaf(xv, w.y, acc[q*4+1]);
            acc[q*4+2] = fmaf(xv, w.z, acc[q*4+2]);
            acc[q*4+3] = fmaf(xv, w.w, acc[q*4+3]);
        }
    }
#pragma unroll
    for (int e = 0; e < 16; e++)
        for (int off = 16; off; off >>= 1)
            acc[e] += __shfl_down_sync(0xffffffffu, acc[e], off);
    __shared__ float ws[8][16];
    int warp = t >> 5, lane = t & 31;
    if (lane == 0)
        for (int e = 0; e < 16; e++) ws[warp][e] = acc[e];
    __syncthreads();
    if (t == 0) {
        float l[16];
        for (int e = 0; e < 16; e++) {
            float s = 0.f;
            for (int w = 0; w < 8; w++) s += ws[w][e];
            l[e] = s;
        }
        int   idx[4];
        float val[4];
        for (int k = 0; k < 4; k++) {
            float best = -INFINITY; int bi = 0;
            for (int e = 0; e < 16; e++) if (l[e] > best) { best = l[e]; bi = e; }
            idx[k] = bi; val[k] = best; l[bi] = -INFINITY;
        }
        float mx = val[0], s = 0.f, ex[4];
        for (int k = 0; k < 4; k++) { ex[k] = expf(val[k] - mx); s += ex[k]; }
        float inv = 1.f / s;
        for (int k = 0; k < 4; k++) {
            float g = ex[k] * inv;
            int a = n * 4 + k;
            g_tk_idx[a]  = idx[k];
            g_tk_gate[a] = g;
            int slot = atomicAdd(&g_cnt[idx[k]], 1);
            g_list[idx[k] * NTOK + slot] = a;
        }
    }
}

// Aux loss
__global__ void loss_kernel(float* __restrict__ d_out) {
    int t = threadIdx.x;
    int w = t >> 5, lane = t & 31;
    float imp = 0.f, ld = 0.f;
    for (int a = lane; a < NA; a += 32) {
        if (g_tk_idx[a] == w) { imp += g_tk_gate[a]; ld += 1.f; }
    }
    for (int off = 16; off; off >>= 1) {
        imp += __shfl_down_sync(0xffffffffu, imp, off);
        ld  += __shfl_down_sync(0xffffffffu, ld,  off);
    }
    __shared__ float simp[16], sld[16];
    if (lane == 0) { simp[w] = imp; sld[w] = ld; }
    __syncthreads();
    if (t == 0) {
        float m1 = 0.f, m2 = 0.f;
        for (int e = 0; e < 16; e++) { m1 += simp[e]; m2 += sld[e]; }
        m1 *= (1.f/16.f); m2 *= (1.f/16.f);
        float v1 = 0.f, v2 = 0.f;
        for (int e = 0; e < 16; e++) {
            float a = simp[e] - m1, b = sld[e] - m2;
            v1 += a * a; v2 += b * b;
        }
        v1 *= (1.f/15.f); v2 *= (1.f/15.f);
        float cv1 = v1 / (m1*m1 + 1e-10f);
        float cv2 = v2 / (m2*m2 + 1e-10f);
        d_out[640] = (cv1 + cv2) * 0.01f;
    }
}

// HMMA bf16 3-split gathered expert GEMM, software-pipelined (double-buffered).
// CTA tile 128(M) x 64(N), KC=64, 8 warps each 32x32.
__global__ void __launch_bounds__(256, 2)
expert_gemm_mma(const float* __restrict__ x,
                const float* __restrict__ W,
                const float* __restrict__ bias,
                int pass1) {
    int e   = blockIdx.z;
    int cnt = g_cnt[e];
    int m0  = blockIdx.y << 7;
    if (m0 >= cnt) return;
    int n0  = blockIdx.x << 6;

    extern __shared__ __align__(16) uint8_t smem[];

    const float* A_base = pass1 ? x : (const float*)g_h;
    float*       C      = pass1 ? g_h : g_o;
    const float* We     = W + (size_t)e * DIM * HID;

    int t = threadIdx.x, wid = t >> 5, lane = t & 31;

    // A staging role: row = t>>1 (128 rows), half = t&1 (32 elems each)
    int arow = t >> 1, ahalf = t & 1;
    int mi_s = m0 + arow;
    int aid_s = (mi_s < cnt) ? g_list[e * NTOK + mi_s] : -1;
    int asrc = 0;
    if (aid_s >= 0) asrc = pass1 ? (aid_s >> 2) : aid_s;
    const float* Arow = A_base + (size_t)asrc * DIM + ahalf * 32;
    // B staging role: krow = t>>2 (64 rows), quarter = t&3 (16 n-elems each)
    int bkr = t >> 2, bq = t & 3;
    const float* Bptr = We + (size_t)bkr * HID + n0 + bq * 16;

    uint32_t sbase = smem_u32(smem);
    int aOff = SWZ(arow, ahalf*64);        // within-stage A offset base (q adds +16)
    int bOff = SWZ(bkr, bq*32);            // within-stage B offset base (h adds +16)

    int wm = wid & 3, wn = wid >> 2;

    float acc[2][4][4];
#pragma unroll
    for (int i = 0; i < 2; i++)
#pragma unroll
        for (int j = 0; j < 4; j++)
#pragma unroll
            for (int q = 0; q < 4; q++) acc[i][j][q] = 0.f;

    float4 fa[8], fb[4];

#define LOAD_REGS(k0)                                                          \
    {                                                                          \
        const float4* ap = (const float4*)(Arow + (k0));                       \
        _Pragma("unroll")                                                      \
        for (int q = 0; q < 8; q++) fa[q] = ap[q];                             \
        const float4* bp = (const float4*)(Bptr + (size_t)(k0) * HID);         \
        _Pragma("unroll")                                                      \
        for (int q = 0; q < 4; q++) fb[q] = bp[q];                             \
    }

#define CONVERT_STORE(stg)                                                     \
    {                                                                          \
        uint8_t* sAhi = smem + (stg)*STAGE_BYTES + S_AHI;                      \
        uint8_t* sAlo = smem + (stg)*STAGE_BYTES + S_ALO;                      \
        uint8_t* sBhi = smem + (stg)*STAGE_BYTES + S_BHI;                      \
        uint8_t* sBlo = smem + (stg)*STAGE_BYTES + S_BLO;                      \
        _Pragma("unroll")                                                      \
        for (int q = 0; q < 4; q++) {                                          \
            float4 u = fa[2*q], v = fa[2*q+1];                                 \
            float pv[8] = {u.x,u.y,u.z,u.w,v.x,v.y,v.z,v.w};                   \
            uint32_t hi[4], lo[4];                                             \
            _Pragma("unroll")                                                  \
            for (int p = 0; p < 4; p++) {                                      \
                __nv_bfloat162 h2 = __floats2bfloat162_rn(pv[2*p], pv[2*p+1]); \
                float2 hf = __bfloat1622float2(h2);                            \
                __nv_bfloat162 l2 = __floats2bfloat162_rn(pv[2*p]-hf.x, pv[2*p+1]-hf.y); \
                hi[p] = *(uint32_t*)&h2; lo[p] = *(uint32_t*)&l2;              \
            }                                                                  \
            int off = aOff + ((q*16) ^ 0);                                     \
            off = SWZ(arow, ahalf*64 + q*16);                                  \
            *(uint4*)(sAhi + off) = make_uint4(hi[0],hi[1],hi[2],hi[3]);       \
            *(uint4*)(sAlo + off) = make_uint4(lo[0],lo[1],lo[2],lo[3]);       \
        }                                                                      \
        _Pragma("unroll")                                                      \
        for (int h = 0; h < 2; h++) {                                          \
            float4 u = fb[2*h], v = fb[2*h+1];                                 \
            float pv[8] = {u.x,u.y,u.z,u.w,v.x,v.y,v.z,v.w};                   \
            uint32_t hi[4], lo[4];                                             \
            _Pragma("unroll")                                                  \
            for (int p = 0; p < 4; p++) {                                      \
                __nv_bfloat162 h2 = __floats2bfloat162_rn(pv[2*p], pv[2*p+1]); \
                float2 hf = __bfloat1622float2(h2);                            \
                __nv_bfloat162 l2 = __floats2bfloat162_rn(pv[2*p]-hf.x, pv[2*p+1]-hf.y); \
                hi[p] = *(uint32_t*)&h2; lo[p] = *(uint32_t*)&l2;              \
            }                                                                  \
            int off = SWZ(bkr, bq*32 + h*16);                                  \
            *(uint4*)(sBhi + off) = make_uint4(hi[0],hi[1],hi[2],hi[3]);       \
            *(uint4*)(sBlo + off) = make_uint4(lo[0],lo[1],lo[2],lo[3]);       \
        }                                                                      \
    }

#define COMPUTE(stg)                                                           \
    {                                                                          \
        uint32_t aHiB = sbase + (stg)*STAGE_BYTES + S_AHI;                     \
        uint32_t aLoB = sbase + (stg)*STAGE_BYTES + S_ALO;                     \
        uint32_t bHiB = sbase + (stg)*STAGE_BYTES + S_BHI;                     \
        uint32_t bLoB = sbase + (stg)*STAGE_BYTES + S_BLO;                     \
        _Pragma("unroll")                                                      \
        for (int ks = 0; ks < 4; ks++) {                                       \
            uint32_t ah[2][4], al[2][4];                                       \
            _Pragma("unroll")                                                  \
            for (int i = 0; i < 2; i++) {                                      \
                int r = wm * 32 + i * 16 + (lane & 15);                        \
                int cb = ks*32 + ((lane >> 4) << 4);                           \
                uint32_t ad = (uint32_t)SWZ(r, cb);                            \
                ldsm4(ah[i][0], ah[i][1], ah[i][2], ah[i][3], aHiB + ad);      \
                ldsm4(al[i][0], al[i][1], al[i][2], al[i][3], aLoB + ad);      \
            }                                                                  \
            uint32_t bh[4][2], bl[4][2];                                       \
            _Pragma("unroll")                                                  \
            for (int jp = 0; jp < 2; jp++) {                                   \
                int r = ks * 16 + (lane & 15);                                 \
                int cb = wn * 64 + jp * 32 + ((lane >> 4) << 4);               \
                uint32_t bd = (uint32_t)SWZ(r, cb);                            \
                uint32_t r0,r1,r2,r3;                                          \
                ldsm4t(r0, r1, r2, r3, bHiB + bd);                             \
                bh[jp*2][0]=r0; bh[jp*2][1]=r1; bh[jp*2+1][0]=r2; bh[jp*2+1][1]=r3; \
                ldsm4t(r0, r1, r2, r3, bLoB + bd);                             \
                bl[jp*2][0]=r0; bl[jp*2][1]=r1; bl[jp*2+1][0]=r2; bl[jp*2+1][1]=r3; \
            }                                                                  \
            _Pragma("unroll")                                                  \
            for (int i = 0; i < 2; i++)                                        \
                _Pragma("unroll")                                              \
                for (int j = 0; j < 4; j++) {                                  \
                    mma16816(acc[i][j], ah[i], bh[j][0], bh[j][1]);            \
                    mma16816(acc[i][j], ah[i], bl[j][0], bl[j][1]);            \
                    mma16816(acc[i][j], al[i], bh[j][0], bh[j][1]);            \
                }                                                              \
        }                                                                      \
    }

    // Prologue: stage chunk 0
    LOAD_REGS(0);
    CONVERT_STORE(0);
    __syncthreads();

    int p = 0;
#pragma unroll 1
    for (int c = 0; c < DIM/64; c++) {
        if (c + 1 < DIM/64) LOAD_REGS((c+1)*64);   // LDG in flight during compute
        COMPUTE(p);
        if (c + 1 < DIM/64) {
            CONVERT_STORE(p ^ 1);                  // consumes LDG results
            __syncthreads();                       // buf p^1 ready; all passed compute(p)
            p ^= 1;
        }
    }

    // Epilogue: scatter-store with bias (+relu pass1)
    int colb = n0 + wn * 32 + (lane & 3) * 2;
    float2 bz[4];
#pragma unroll
    for (int j = 0; j < 4; j++)
        bz[j] = *(const float2*)(bias + e * HID + colb + j * 8);

#pragma unroll
    for (int i = 0; i < 2; i++) {
#pragma unroll
        for (int rh = 0; rh < 2; rh++) {
            int row = wm * 32 + i * 16 + rh * 8 + (lane >> 2);
            int mi = m0 + row;
            int aid = (mi < cnt) ? g_list[e * NTOK + mi] : -1;
            if (aid < 0) continue;
            float* Crow = C + (size_t)aid * HID;
#pragma unroll
            for (int j = 0; j < 4; j++) {
                float2 o;
                o.x = acc[i][j][rh*2+0] + bz[j].x;
                o.y = acc[i][j][rh*2+1] + bz[j].y;
                if (pass1) { o.x = fmaxf(o.x, 0.f); o.y = fmaxf(o.y, 0.f); }
                *(float2*)(Crow + colb + j * 8) = o;
            }
        }
    }
#undef LOAD_REGS
#undef CONVERT_STORE
#undef COMPUTE
}

__device__ float block_reduce_256(float v, volatile float* red) {
    int t = threadIdx.x;
    red[t] = v; __syncthreads();
    if (t < 128) red[t] += red[t + 128]; __syncthreads();
    if (t <  64) red[t] += red[t +  64]; __syncthreads();
    if (t <  32) {
        red[t] += red[t + 32]; __syncwarp();
        red[t] += red[t + 16]; __syncwarp();
        red[t] += red[t +  8]; __syncwarp();
        red[t] += red[t +  4]; __syncwarp();
        red[t] += red[t +  2]; __syncwarp();
        red[t] += red[t +  1]; __syncwarp();
    }
    __syncthreads();
    float r = red[0];
    __syncthreads();
    return r;
}

__global__ void finalize_kernel(const float* __restrict__ ln_w,
                                const float* __restrict__ ln_b,
                                const float* __restrict__ W_los,
                                const float* __restrict__ b_los,
                                float* __restrict__ d_out) {
    __shared__ float red[256];
    int b = blockIdx.x, t = threadIdx.x;
    float v[4];
#pragma unroll
    for (int i = 0; i < 4; i++) {
        int d = t + (i << 8);
        float acc = 0.f;
        for (int m = 0; m < NM; m++) {
            int n = (b << 4) + m;
#pragma unroll
            for (int k = 0; k < 4; k++) {
                int a = (n << 2) + k;
                acc = fmaf(g_tk_gate[a], g_o[(size_t)a * DIM + d], acc);
            }
        }
        v[i] = acc;
    }
    float s = 0.f, ss = 0.f;
#pragma unroll
    for (int i = 0; i < 4; i++) { s += v[i]; ss = fmaf(v[i], v[i], ss); }
    float sum   = block_reduce_256(s,  red);
    float sumsq = block_reduce_256(ss, red);
    float mu   = sum * (1.f / 1024.f);
    float var  = sumsq * (1.f / 1024.f) - mu * mu;
    float rstd = 1.f / sqrtf(var + 1e-5f);

    float sc[10];
#pragma unroll
    for (int o = 0; o < 10; o++) sc[o] = 0.f;
#pragma unroll
    for (int i = 0; i < 4; i++) {
        int d = t + (i << 8);
        float f = (v[i] - mu) * rstd * ln_w[d] + ln_b[d];
        const float* wl = W_los + (size_t)d * NOUT;
#pragma unroll
        for (int o = 0; o < 10; o++) sc[o] = fmaf(f, wl[o], sc[o]);
    }
    for (int o = 0; o < 10; o++) {
        float r = block_reduce_256(sc[o], red);
        if (t == 0) d_out[b * NOUT + o] = r + b_los[o];
    }
}

__global__ void predloss_kernel(const float* __restrict__ true_y, float* __restrict__ d_out) {
    __shared__ float red[256];
    int t = threadIdx.x;
    float s = 0.f;
    for (int i = t; i < NB * NOUT; i += 256) {
        float dd = d_out[i] - true_y[i];
        s = fmaf(dd, dd, s);
    }
    float r = block_reduce_256(s, red);
    if (t == 0) d_out[641] = r * (1.f / 640.f);
}

extern "C" void kernel_launch(void* const* d_in, const int* in_sizes, int n_in,
                              void* d_out, int out_size) {
    const float* x      = (const float*)d_in[0];
    const float* wg     = (const float*)d_in[1];
    const float* W1     = (const float*)d_in[2];
    const float* b1     = (const float*)d_in[3];
    const float* W2     = (const float*)d_in[4];
    const float* b2     = (const float*)d_in[5];
    const float* ln_w   = (const float*)d_in[6];
    const float* ln_b   = (const float*)d_in[7];
    const float* W_los  = (const float*)d_in[8];
    const float* b_los  = (const float*)d_in[9];
    const float* true_y = (const float*)d_in[10];
    float* out = (float*)d_out;

    static int smem_set = 0;
    if (!smem_set) {
        cudaFuncSetAttribute(expert_gemm_mma,
                             cudaFuncAttributeMaxDynamicSharedMemorySize, SMEM_TOTAL);
        smem_set = 1;
    }

    init_kernel<<<1, 32>>>();
    gate_kernel<<<NTOK, 256>>>(x, wg);
    loss_kernel<<<1, 512>>>(out);
    expert_gemm_mma<<<dim3(16, 8, 16), 256, SMEM_TOTAL>>>(x, W1, b1, 1);
    expert_gemm_mma<<<dim3(16, 8, 16), 256, SMEM_TOTAL>>>(x, W2, b2, 0);
    finalize_kernel<<<64, 256>>>(ln_w, ln_b, W_los, b_los, out);
    predloss_kernel<<<1, 256>>>(true_y, out);
}

// round 6
// speedup vs baseline: 2.3463x; 1.4016x over previous
#include <cuda_runtime.h>
#include <cuda_fp16.h>
#include <math.h>
#include <stdint.h>

// Problem constants
#define NTOK 1024
#define DIM  1024
#define HID  1024
#define NE   16
#define NK   4
#define NA   (NTOK*NK)
#define NOUT 10
#define NB   64
#define NM   16

// Scratch (device globals: allocation-free)
__device__ __align__(16) __half g_x16[(size_t)NTOK*DIM];  // 2 MB: x in fp16
__device__ __align__(16) __half g_h16[(size_t)NA*HID];    // 8 MB: relu(x@W1+b1) fp16
__device__ __align__(16) float  g_o[(size_t)NA*DIM];      // 16 MB
__device__ int   g_tk_idx[NA];
__device__ float g_tk_gate[NA];
__device__ int   g_cnt[NE];
__device__ int   g_list[NE*NTOK];

__device__ __forceinline__ uint32_t smem_u32(const void* p) {
    uint32_t a;
    asm("{ .reg .u64 t; cvta.to.shared.u64 t, %1; cvt.u32.u64 %0, t; }" : "=r"(a) : "l"(p));
    return a;
}
__device__ __forceinline__ void ldsm4(uint32_t& r0, uint32_t& r1, uint32_t& r2, uint32_t& r3, uint32_t a) {
    asm volatile("ldmatrix.sync.aligned.m8n8.x4.shared.b16 {%0,%1,%2,%3}, [%4];"
                 : "=r"(r0), "=r"(r1), "=r"(r2), "=r"(r3) : "r"(a));
}
__device__ __forceinline__ void ldsm4t(uint32_t& r0, uint32_t& r1, uint32_t& r2, uint32_t& r3, uint32_t a) {
    asm volatile("ldmatrix.sync.aligned.m8n8.x4.trans.shared.b16 {%0,%1,%2,%3}, [%4];"
                 : "=r"(r0), "=r"(r1), "=r"(r2), "=r"(r3) : "r"(a));
}
__device__ __forceinline__ void mma16816(float* c, const uint32_t* a, uint32_t b0, uint32_t b1) {
    asm volatile("mma.sync.aligned.m16n8k16.row.col.f32.f16.f16.f32 "
                 "{%0,%1,%2,%3}, {%4,%5,%6,%7}, {%8,%9}, {%0,%1,%2,%3};"
                 : "+f"(c[0]), "+f"(c[1]), "+f"(c[2]), "+f"(c[3])
                 : "r"(a[0]), "r"(a[1]), "r"(a[2]), "r"(a[3]), "r"(b0), "r"(b1));
}

// XOR swizzles: keep each 8-row ldsm phase conflict-free
#define SWZ(row, cb)    ((row)*128 + ((cb) ^ (((row)&7)<<4)))   // 128B rows (A)
#define SWZ256(row, cb) ((row)*256 + ((cb) ^ (((row)&7)<<4)))   // 256B rows (B)

// stage layout (bytes): Ahi 16KB | Bhi 16KB | Blo 16KB
#define S_AHI 0
#define S_BHI (128*128)
#define S_BLO (128*128 + 64*256)
#define STAGE_BYTES (128*128 + 2*64*256)      // 48KB
#define SMEM_TOTAL  (2*STAGE_BYTES)           // 96KB

__global__ void init_kernel() {
    if (threadIdx.x < NE) g_cnt[threadIdx.x] = 0;
}

// x fp32 -> fp16 (once per launch)
__global__ void convert_x_kernel(const float* __restrict__ x) {
    int g = blockIdx.x * 256 + threadIdx.x;      // 256 blocks: 16 elems each
    const float4* xp = (const float4*)(x + (size_t)g * 16);
    __half2 h[8];
#pragma unroll
    for (int q = 0; q < 4; q++) {
        float4 v = xp[q];
        h[2*q+0] = __float22half2_rn(make_float2(v.x, v.y));
        h[2*q+1] = __float22half2_rn(make_float2(v.z, v.w));
    }
    uint4* op = (uint4*)(g_x16 + (size_t)g * 16);
    op[0] = *(uint4*)&h[0];
    op[1] = *(uint4*)&h[4];
}

// One block per token: logits = x_row @ w_gate, top-4, softmax, routing lists.
__global__ void gate_kernel(const float* __restrict__ x, const float* __restrict__ wg) {
    int n = blockIdx.x;
    int t = threadIdx.x;               // 256 threads
    float acc[16];
#pragma unroll
    for (int e = 0; e < 16; e++) acc[e] = 0.f;
    const float* xr = x + (size_t)n * DIM;
    for (int d = t; d < DIM; d += 256) {
        float xv = xr[d];
        const float4* w4 = (const float4*)(wg + (size_t)d * 16);
#pragma unroll
        for (int q = 0; q < 4; q++) {
            float4 w = w4[q];
            acc[q*4+0] = fmaf(xv, w.x, acc[q*4+0]);
            acc[q*4+1] = fmaf(xv, w.y, acc[q*4+1]);
            acc[q*4+2] = fmaf(xv, w.z, acc[q*4+2]);
            acc[q*4+3] = fmaf(xv, w.w, acc[q*4+3]);
        }
    }
#pragma unroll
    for (int e = 0; e < 16; e++)
        for (int off = 16; off; off >>= 1)
            acc[e] += __shfl_down_sync(0xffffffffu, acc[e], off);
    __shared__ float ws[8][16];
    int warp = t >> 5, lane = t & 31;
    if (lane == 0)
        for (int e = 0; e < 16; e++) ws[warp][e] = acc[e];
    __syncthreads();
    if (t == 0) {
        float l[16];
        for (int e = 0; e < 16; e++) {
            float s = 0.f;
            for (int w = 0; w < 8; w++) s += ws[w][e];
            l[e] = s;
        }
        int   idx[4];
        float val[4];
        for (int k = 0; k < 4; k++) {
            float best = -INFINITY; int bi = 0;
            for (int e = 0; e < 16; e++) if (l[e] > best) { best = l[e]; bi = e; }
            idx[k] = bi; val[k] = best; l[bi] = -INFINITY;
        }
        float mx = val[0], s = 0.f, ex[4];
        for (int k = 0; k < 4; k++) { ex[k] = expf(val[k] - mx); s += ex[k]; }
        float inv = 1.f / s;
        for (int k = 0; k < 4; k++) {
            float g = ex[k] * inv;
            int a = n * 4 + k;
            g_tk_idx[a]  = idx[k];
            g_tk_gate[a] = g;
            int slot = atomicAdd(&g_cnt[idx[k]], 1);
            g_list[idx[k] * NTOK + slot] = a;
        }
    }
}

// Aux loss
__global__ void loss_kernel(float* __restrict__ d_out) {
    int t = threadIdx.x;
    int w = t >> 5, lane = t & 31;
    float imp = 0.f, ld = 0.f;
    for (int a = lane; a < NA; a += 32) {
        if (g_tk_idx[a] == w) { imp += g_tk_gate[a]; ld += 1.f; }
    }
    for (int off = 16; off; off >>= 1) {
        imp += __shfl_down_sync(0xffffffffu, imp, off);
        ld  += __shfl_down_sync(0xffffffffu, ld,  off);
    }
    __shared__ float simp[16], sld[16];
    if (lane == 0) { simp[w] = imp; sld[w] = ld; }
    __syncthreads();
    if (t == 0) {
        float m1 = 0.f, m2 = 0.f;
        for (int e = 0; e < 16; e++) { m1 += simp[e]; m2 += sld[e]; }
        m1 *= (1.f/16.f); m2 *= (1.f/16.f);
        float v1 = 0.f, v2 = 0.f;
        for (int e = 0; e < 16; e++) {
            float a = simp[e] - m1, b = sld[e] - m2;
            v1 += a * a; v2 += b * b;
        }
        v1 *= (1.f/15.f); v2 *= (1.f/15.f);
        float cv1 = v1 / (m1*m1 + 1e-10f);
        float cv2 = v2 / (m2*m2 + 1e-10f);
        d_out[640] = (cv1 + cv2) * 0.01f;
    }
}

// fp16 2-term split expert GEMM: D = A * (Bhi + Blo), A fp16 (pre-converted),
// B = fp32 weights split in-kernel. CTA 128(M) x 128(N), KC=64, double-buffered.
// 8 warps = 2(m) x 4(n), warp tile 64x32.
// pass1: A=g_x16 (row aid>>2) -> g_h16 (+b1, relu, fp16).
// pass2: A=g_h16 (row aid)    -> g_o   (+b2, fp32).
__global__ void __launch_bounds__(256, 1)
expert_gemm_mma(const float* __restrict__ W,
                const float* __restrict__ bias,
                int pass1) {
    int e   = blockIdx.z;
    int cnt = g_cnt[e];
    int m0  = blockIdx.y << 7;
    if (m0 >= cnt) return;
    int n0  = blockIdx.x << 7;

    extern __shared__ __align__(16) uint8_t smem[];
    __shared__ int rowid[128];

    const float* We = W + (size_t)e * DIM * HID;

    int t = threadIdx.x, wid = t >> 5, lane = t & 31;

    if (t < 128) {
        int mi = m0 + t;
        rowid[t] = (mi < cnt) ? g_list[e * NTOK + mi] : -1;
    }
    __syncthreads();

    // A staging: row = t>>1 (128 rows), half = t&1 (32 fp16 = 64B each)
    int arow = t >> 1, ahalf = t & 1;
    int aid_s = rowid[arow];
    int asrc = 0;
    if (aid_s >= 0) asrc = pass1 ? (aid_s >> 2) : aid_s;
    const __half* Arow = (pass1 ? g_x16 : g_h16) + (size_t)asrc * DIM + ahalf * 32;
    // B staging: krow = t>>2 (64 rows), quarter = t&3 (32 n fp32 = 128B each)
    int bkr = t >> 2, bq = t & 3;
    const float* Bptr = We + (size_t)bkr * HID + n0 + bq * 32;

    uint32_t sbase = smem_u32(smem);
    int wm = wid & 1, wn = wid >> 1;

    float acc[4][4][4];
#pragma unroll
    for (int i = 0; i < 4; i++)
#pragma unroll
        for (int j = 0; j < 4; j++)
#pragma unroll
            for (int q = 0; q < 4; q++) acc[i][j][q] = 0.f;

    uint4  ua[4];     // A: 64B of fp16
    float4 fb[8];     // B: 128B of fp32

#define LOAD_REGS(k0)                                                          \
    {                                                                          \
        const uint4* ap = (const uint4*)(Arow + (k0));                         \
        _Pragma("unroll")                                                      \
        for (int q = 0; q < 4; q++) ua[q] = ap[q];                             \
        const float4* bp = (const float4*)(Bptr + (size_t)(k0) * HID);         \
        _Pragma("unroll")                                                      \
        for (int q = 0; q < 8; q++) fb[q] = bp[q];                             \
    }

#define CONVERT_STORE(stg)                                                     \
    {                                                                          \
        uint8_t* sAhi = smem + (stg)*STAGE_BYTES + S_AHI;                      \
        uint8_t* sBhi = smem + (stg)*STAGE_BYTES + S_BHI;                      \
        uint8_t* sBlo = smem + (stg)*STAGE_BYTES + S_BLO;                      \
        _Pragma("unroll")                                                      \
        for (int q = 0; q < 4; q++)                                            \
            *(uint4*)(sAhi + SWZ(arow, ahalf*64 + q*16)) = ua[q];              \
        _Pragma("unroll")                                                      \
        for (int q = 0; q < 8; q++) {                                          \
            float4 v = fb[q];                                                  \
            __half2 h0 = __float22half2_rn(make_float2(v.x, v.y));             \
            __half2 h1 = __float22half2_rn(make_float2(v.z, v.w));             \
            float2 f0 = __half22float2(h0), f1 = __half22float2(h1);           \
            __half2 l0 = __float22half2_rn(make_float2(v.x-f0.x, v.y-f0.y));   \
            __half2 l1 = __float22half2_rn(make_float2(v.z-f1.x, v.w-f1.y));   \
            int off = SWZ256(bkr, bq*64 + q*8);                                \
            *(uint2*)(sBhi + off) = make_uint2(*(uint32_t*)&h0, *(uint32_t*)&h1); \
            *(uint2*)(sBlo + off) = make_uint2(*(uint32_t*)&l0, *(uint32_t*)&l1); \
        }                                                                      \
    }

#define COMPUTE(stg)                                                           \
    {                                                                          \
        uint32_t aHiB = sbase + (stg)*STAGE_BYTES + S_AHI;                     \
        uint32_t bHiB = sbase + (stg)*STAGE_BYTES + S_BHI;                     \
        uint32_t bLoB = sbase + (stg)*STAGE_BYTES + S_BLO;                     \
        _Pragma("unroll")                                                      \
        for (int ks = 0; ks < 4; ks++) {                                       \
            uint32_t ah[4][4];                                                 \
            _Pragma("unroll")                                                  \
            for (int i = 0; i < 4; i++) {                                      \
                int r = wm * 64 + i * 16 + (lane & 15);                        \
                int cb = ks*32 + ((lane >> 4) << 4);                           \
                ldsm4(ah[i][0], ah[i][1], ah[i][2], ah[i][3],                  \
                      aHiB + (uint32_t)SWZ(r, cb));                            \
            }                                                                  \
            uint32_t bh[4][2], bl[4][2];                                       \
            _Pragma("unroll")                                                  \
            for (int jp = 0; jp < 2; jp++) {                                   \
                int r = ks * 16 + (lane & 15);                                 \
                int cb = wn * 64 + jp * 32 + ((lane >> 4) << 4);               \
                uint32_t ad = (uint32_t)SWZ256(r, cb);                         \
                uint32_t r0,r1,r2,r3;                                          \
                ldsm4t(r0, r1, r2, r3, bHiB + ad);                             \
                bh[jp*2][0]=r0; bh[jp*2][1]=r1; bh[jp*2+1][0]=r2; bh[jp*2+1][1]=r3; \
                ldsm4t(r0, r1, r2, r3, bLoB + ad);                             \
                bl[jp*2][0]=r0; bl[jp*2][1]=r1; bl[jp*2+1][0]=r2; bl[jp*2+1][1]=r3; \
            }                                                                  \
            _Pragma("unroll")                                                  \
            for (int i = 0; i < 4; i++)                                        \
                _Pragma("unroll")                                              \
                for (int j = 0; j < 4; j++) {                                  \
                    mma16816(acc[i][j], ah[i], bh[j][0], bh[j][1]);            \
                    mma16816(acc[i][j], ah[i], bl[j][0], bl[j][1]);            \
                }                                                              \
        }                                                                      \
    }

    LOAD_REGS(0);
    CONVERT_STORE(0);
    __syncthreads();

    int p = 0;
#pragma unroll 1
    for (int c = 0; c < DIM/64; c++) {
        if (c + 1 < DIM/64) LOAD_REGS((c+1)*64);
        COMPUTE(p);
        if (c + 1 < DIM/64) {
            CONVERT_STORE(p ^ 1);
            __syncthreads();
            p ^= 1;
        }
    }

    // Epilogue
    int colb = wn * 32 + (lane & 3) * 2;     // elem offset within CTA N tile
    float2 bz[4];
#pragma unroll
    for (int j = 0; j < 4; j++)
        bz[j] = *(const float2*)(bias + e * HID + n0 + colb + j * 8);

#pragma unroll
    for (int i = 0; i < 4; i++) {
#pragma unroll
        for (int rh = 0; rh < 2; rh++) {
            int row = wm * 64 + i * 16 + rh * 8 + (lane >> 2);
            int aid = rowid[row];
            if (aid < 0) continue;
#pragma unroll
            for (int j = 0; j < 4; j++) {
                float ox = acc[i][j][rh*2+0] + bz[j].x;
                float oy = acc[i][j][rh*2+1] + bz[j].y;
                if (pass1) {
                    ox = fmaxf(ox, 0.f); oy = fmaxf(oy, 0.f);
                    __half2 h = __float22half2_rn(make_float2(ox, oy));
                    *(__half2*)(g_h16 + (size_t)aid * HID + n0 + colb + j * 8) = h;
                } else {
                    *(float2*)(g_o + (size_t)aid * DIM + n0 + colb + j * 8) = make_float2(ox, oy);
                }
            }
        }
    }
#undef LOAD_REGS
#undef CONVERT_STORE
#undef COMPUTE
}

__device__ float block_reduce_256(float v, volatile float* red) {
    int t = threadIdx.x;
    red[t] = v; __syncthreads();
    if (t < 128) red[t] += red[t + 128]; __syncthreads();
    if (t <  64) red[t] += red[t +  64]; __syncthreads();
    if (t <  32) {
        red[t] += red[t + 32]; __syncwarp();
        red[t] += red[t + 16]; __syncwarp();
        red[t] += red[t +  8]; __syncwarp();
        red[t] += red[t +  4]; __syncwarp();
        red[t] += red[t +  2]; __syncwarp();
        red[t] += red[t +  1]; __syncwarp();
    }
    __syncthreads();
    float r = red[0];
    __syncthreads();
    return r;
}

__global__ void finalize_kernel(const float* __restrict__ ln_w,
                                const float* __restrict__ ln_b,
                                const float* __restrict__ W_los,
                                const float* __restrict__ b_los,
                                float* __restrict__ d_out) {
    __shared__ float red[256];
    int b = blockIdx.x, t = threadIdx.x;
    float v[4];
#pragma unroll
    for (int i = 0; i < 4; i++) {
        int d = t + (i << 8);
        float acc = 0.f;
        for (int m = 0; m < NM; m++) {
            int n = (b << 4) + m;
#pragma unroll
            for (int k = 0; k < 4; k++) {
                int a = (n << 2) + k;
                acc = fmaf(g_tk_gate[a], g_o[(size_t)a * DIM + d], acc);
            }
        }
        v[i] = acc;
    }
    float s = 0.f, ss = 0.f;
#pragma unroll
    for (int i = 0; i < 4; i++) { s += v[i]; ss = fmaf(v[i], v[i], ss); }
    float sum   = block_reduce_256(s,  red);
    float sumsq = block_reduce_256(ss, red);
    float mu   = sum * (1.f / 1024.f);
    float var  = sumsq * (1.f / 1024.f) - mu * mu;
    float rstd = 1.f / sqrtf(var + 1e-5f);

    float sc[10];
#pragma unroll
    for (int o = 0; o < 10; o++) sc[o] = 0.f;
#pragma unroll
    for (int i = 0; i < 4; i++) {
        int d = t + (i << 8);
        float f = (v[i] - mu) * rstd * ln_w[d] + ln_b[d];
        const float* wl = W_los + (size_t)d * NOUT;
#pragma unroll
        for (int o = 0; o < 10; o++) sc[o] = fmaf(f, wl[o], sc[o]);
    }
    for (int o = 0; o < 10; o++) {
        float r = block_reduce_256(sc[o], red);
        if (t == 0) d_out[b * NOUT + o] = r + b_los[o];
    }
}

__global__ void predloss_kernel(const float* __restrict__ true_y, float* __restrict__ d_out) {
    __shared__ float red[256];
    int t = threadIdx.x;
    float s = 0.f;
    for (int i = t; i < NB * NOUT; i += 256) {
        float dd = d_out[i] - true_y[i];
        s = fmaf(dd, dd, s);
    }
    float r = block_reduce_256(s, red);
    if (t == 0) d_out[641] = r * (1.f / 640.f);
}

extern "C" void kernel_launch(void* const* d_in, const int* in_sizes, int n_in,
                              void* d_out, int out_size) {
    const float* x      = (const float*)d_in[0];
    const float* wg     = (const float*)d_in[1];
    const float* W1     = (const float*)d_in[2];
    const float* b1     = (const float*)d_in[3];
    const float* W2     = (const float*)d_in[4];
    const float* b2     = (const float*)d_in[5];
    const float* ln_w   = (const float*)d_in[6];
    const float* ln_b   = (const float*)d_in[7];
    const float* W_los  = (const float*)d_in[8];
    const float* b_los  = (const float*)d_in[9];
    const float* true_y = (const float*)d_in[10];
    float* out = (float*)d_out;

    static int smem_set = 0;
    if (!smem_set) {
        cudaFuncSetAttribute(expert_gemm_mma,
                             cudaFuncAttributeMaxDynamicSharedMemorySize, SMEM_TOTAL);
        smem_set = 1;
    }

    init_kernel<<<1, 32>>>();
    convert_x_kernel<<<256, 256>>>(x);
    gate_kernel<<<NTOK, 256>>>(x, wg);
    loss_kernel<<<1, 512>>>(out);
    expert_gemm_mma<<<dim3(8, 8, 16), 256, SMEM_TOTAL>>>(W1, b1, 1);
    expert_gemm_mma<<<dim3(8, 8, 16), 256, SMEM_TOTAL>>>(W2, b2, 0);
    finalize_kernel<<<64, 256>>>(ln_w, ln_b, W_los, b_los, out);
    predloss_kernel<<<1, 256>>>(true_y, out);
}

// round 7
// speedup vs baseline: 2.7393x; 1.1675x over previous
#include <cuda_runtime.h>
#include <cuda_fp16.h>
#include <math.h>
#include <stdint.h>

// Problem constants
#define NTOK 1024
#define DIM  1024
#define HID  1024
#define NE   16
#define NK   4
#define NA   (NTOK*NK)
#define NOUT 10
#define NB   64
#define NM   16

// Scratch (device globals: allocation-free)
__device__ __align__(16) __half g_x16[(size_t)NTOK*DIM];  // 2 MB: x in fp16
__device__ __align__(16) __half g_h16[(size_t)NA*HID];    // 8 MB: relu(x@W1+b1) fp16
__device__ __align__(16) float  g_o[(size_t)NA*DIM];      // 16 MB
__device__ int   g_tk_idx[NA];
__device__ float g_tk_gate[NA];
__device__ int   g_cnt[NE];
__device__ int   g_list[NE*NTOK];
__device__ float g_imp[NE];
__device__ float g_ld[NE];

__device__ __forceinline__ uint32_t smem_u32(const void* p) {
    uint32_t a;
    asm("{ .reg .u64 t; cvta.to.shared.u64 t, %1; cvt.u32.u64 %0, t; }" : "=r"(a) : "l"(p));
    return a;
}
__device__ __forceinline__ void ldsm4(uint32_t& r0, uint32_t& r1, uint32_t& r2, uint32_t& r3, uint32_t a) {
    asm volatile("ldmatrix.sync.aligned.m8n8.x4.shared.b16 {%0,%1,%2,%3}, [%4];"
                 : "=r"(r0), "=r"(r1), "=r"(r2), "=r"(r3) : "r"(a));
}
__device__ __forceinline__ void ldsm4t(uint32_t& r0, uint32_t& r1, uint32_t& r2, uint32_t& r3, uint32_t a) {
    asm volatile("ldmatrix.sync.aligned.m8n8.x4.trans.shared.b16 {%0,%1,%2,%3}, [%4];"
                 : "=r"(r0), "=r"(r1), "=r"(r2), "=r"(r3) : "r"(a));
}
__device__ __forceinline__ void mma16816(float* c, const uint32_t* a, uint32_t b0, uint32_t b1) {
    asm volatile("mma.sync.aligned.m16n8k16.row.col.f32.f16.f16.f32 "
                 "{%0,%1,%2,%3}, {%4,%5,%6,%7}, {%8,%9}, {%0,%1,%2,%3};"
                 : "+f"(c[0]), "+f"(c[1]), "+f"(c[2]), "+f"(c[3])
                 : "r"(a[0]), "r"(a[1]), "r"(a[2]), "r"(a[3]), "r"(b0), "r"(b1));
}
__device__ __forceinline__ void cp_async16(uint32_t dst, const void* src) {
    asm volatile("cp.async.cg.shared.global [%0], [%1], 16;" :: "r"(dst), "l"(src));
}
#define CP_COMMIT() asm volatile("cp.async.commit_group;" ::: "memory")
#define CP_WAIT0()  asm volatile("cp.async.wait_group 0;" ::: "memory")

// Swizzles (conflict-free ldsm phases)
// A: 64B rows (32 fp16). granule col bits 4-5; XOR with (row>>1)&3.
#define SWZA(row, cb)   ((row)*64  + ((cb) ^ ((((row)>>1)&3)<<4)))
// B: 256B rows (128 fp16). granule col bits 4-6; XOR with row&7.
#define SWZB(row, cb)   ((row)*256 + ((cb) ^ (((row)&7)<<4)))

// stage layout (bytes): A 8KB | Bhi 8KB | Blo 8KB   (KC=32)
#define S_A   0
#define S_BHI (128*64)
#define S_BLO (128*64 + 32*256)
#define STAGE_BYTES (128*64 + 2*32*256)       // 24KB
#define SMEM_TOTAL  (2*STAGE_BYTES)           // 48KB -> 2 CTAs/SM

__global__ void init_kernel() {
    if (threadIdx.x < NE) g_cnt[threadIdx.x] = 0;
}

// One block per token: logits, top-4, softmax, routing; also x -> fp16.
__global__ void gate_kernel(const float* __restrict__ x, const float* __restrict__ wg) {
    int n = blockIdx.x;
    int t = threadIdx.x;               // 256 threads
    float acc[16];
#pragma unroll
    for (int e = 0; e < 16; e++) acc[e] = 0.f;
    const float* xr = x + (size_t)n * DIM;
    __half* xo = g_x16 + (size_t)n * DIM;
    for (int d = t; d < DIM; d += 256) {
        float xv = xr[d];
        xo[d] = __float2half_rn(xv);           // fused fp16 conversion
        const float4* w4 = (const float4*)(wg + (size_t)d * 16);
#pragma unroll
        for (int q = 0; q < 4; q++) {
            float4 w = w4[q];
            acc[q*4+0] = fmaf(xv, w.x, acc[q*4+0]);
            acc[q*4+1] = fmaf(xv, w.y, acc[q*4+1]);
            acc[q*4+2] = fmaf(xv, w.z, acc[q*4+2]);
            acc[q*4+3] = fmaf(xv, w.w, acc[q*4+3]);
        }
    }
#pragma unroll
    for (int e = 0; e < 16; e++)
        for (int off = 16; off; off >>= 1)
            acc[e] += __shfl_down_sync(0xffffffffu, acc[e], off);
    __shared__ float ws[8][16];
    int warp = t >> 5, lane = t & 31;
    if (lane == 0)
        for (int e = 0; e < 16; e++) ws[warp][e] = acc[e];
    __syncthreads();
    if (t == 0) {
        float l[16];
        for (int e = 0; e < 16; e++) {
            float s = 0.f;
            for (int w = 0; w < 8; w++) s += ws[w][e];
            l[e] = s;
        }
        int   idx[4];
        float val[4];
        for (int k = 0; k < 4; k++) {
            float best = -INFINITY; int bi = 0;
            for (int e = 0; e < 16; e++) if (l[e] > best) { best = l[e]; bi = e; }
            idx[k] = bi; val[k] = best; l[bi] = -INFINITY;
        }
        float mx = val[0], s = 0.f, ex[4];
        for (int k = 0; k < 4; k++) { ex[k] = expf(val[k] - mx); s += ex[k]; }
        float inv = 1.f / s;
        for (int k = 0; k < 4; k++) {
            float g = ex[k] * inv;
            int a = n * 4 + k;
            g_tk_idx[a]  = idx[k];
            g_tk_gate[a] = g;
            int slot = atomicAdd(&g_cnt[idx[k]], 1);
            g_list[idx[k] * NTOK + slot] = a;
        }
    }
}

// Aux loss part 1: one block per expert, deterministic strided reduce.
__global__ void loss_part_kernel() {
    int e = blockIdx.x, t = threadIdx.x;       // 256 threads
    float imp = 0.f, ld = 0.f;
    for (int a = t; a < NA; a += 256) {
        if (g_tk_idx[a] == e) { imp += g_tk_gate[a]; ld += 1.f; }
    }
    __shared__ float si[256], sl[256];
    si[t] = imp; sl[t] = ld; __syncthreads();
    for (int off = 128; off; off >>= 1) {
        if (t < off) { si[t] += si[t+off]; sl[t] += sl[t+off]; }
        __syncthreads();
    }
    if (t == 0) { g_imp[e] = si[0]; g_ld[e] = sl[0]; }
}

// Aux loss part 2: cv^2 combine (1 warp).
__global__ void loss_final_kernel(float* __restrict__ d_out) {
    if (threadIdx.x == 0) {
        float m1 = 0.f, m2 = 0.f;
        for (int e = 0; e < 16; e++) { m1 += g_imp[e]; m2 += g_ld[e]; }
        m1 *= (1.f/16.f); m2 *= (1.f/16.f);
        float v1 = 0.f, v2 = 0.f;
        for (int e = 0; e < 16; e++) {
            float a = g_imp[e] - m1, b = g_ld[e] - m2;
            v1 += a * a; v2 += b * b;
        }
        v1 *= (1.f/15.f); v2 *= (1.f/15.f);
        float cv1 = v1 / (m1*m1 + 1e-10f);
        float cv2 = v2 / (m2*m2 + 1e-10f);
        d_out[640] = (cv1 + cv2) * 0.01f;
    }
}

// fp16 2-term split expert GEMM: D = A * (Bhi + Blo).
// CTA 128(M) x 128(N), KC=32, double-buffered, A via cp.async, 2 CTAs/SM.
// 8 warps = 2(m) x 4(n), warp tile 64x32.
__global__ void __launch_bounds__(256, 2)
expert_gemm_mma(const float* __restrict__ W,
                const float* __restrict__ bias,
                int pass1) {
    int e   = blockIdx.z;
    int cnt = g_cnt[e];
    int m0  = blockIdx.y << 7;
    if (m0 >= cnt) return;
    int n0  = blockIdx.x << 7;

    extern __shared__ __align__(16) uint8_t smem[];
    __shared__ int rowid[128];

    const float* We = W + (size_t)e * DIM * HID;

    int t = threadIdx.x, wid = t >> 5, lane = t & 31;

    if (t < 128) {
        int mi = m0 + t;
        rowid[t] = (mi < cnt) ? g_list[e * NTOK + mi] : -1;
    }
    __syncthreads();

    // A staging: row = t>>1, half = t&1 (16 fp16 = 32B each; 2 x cp.async 16B)
    int arow = t >> 1, ahalf = t & 1;
    int aid_s = rowid[arow];
    int asrc = 0;
    if (aid_s >= 0) asrc = pass1 ? (aid_s >> 2) : aid_s;
    const __half* Arow = (pass1 ? g_x16 : g_h16) + (size_t)asrc * DIM + ahalf * 16;
    uint32_t aDst0 = (uint32_t)SWZA(arow, ahalf*32);
    uint32_t aDst1 = (uint32_t)SWZA(arow, ahalf*32 + 16);
    // B staging: krow = t>>3 (32 rows), seg = t&3? -> 8 threads/row, 16 floats each
    int bkr = t >> 3, bseg = t & 7;
    const float* Bptr = We + (size_t)bkr * HID + n0 + bseg * 16;
    int bOff0 = SWZB(bkr, bseg*32);
    int bOff1 = SWZB(bkr, bseg*32 + 16);

    uint32_t sbase = smem_u32(smem);
    int wm = wid & 1, wn = wid >> 1;

    float acc[4][4][4];
#pragma unroll
    for (int i = 0; i < 4; i++)
#pragma unroll
        for (int j = 0; j < 4; j++)
#pragma unroll
            for (int q = 0; q < 4; q++) acc[i][j][q] = 0.f;

    float4 fb[4];    // B: 64B of fp32

#define ISSUE_A(k0, stg)                                                       \
    {                                                                          \
        uint32_t dA = sbase + (stg)*STAGE_BYTES + S_A;                         \
        cp_async16(dA + aDst0, Arow + (k0));                                   \
        cp_async16(dA + aDst1, Arow + (k0) + 8);                               \
        CP_COMMIT();                                                           \
    }

#define LOAD_B(k0)                                                             \
    {                                                                          \
        const float4* bp = (const float4*)(Bptr + (size_t)(k0) * HID);         \
        _Pragma("unroll")                                                      \
        for (int q = 0; q < 4; q++) fb[q] = bp[q];                             \
    }

#define STORE_B(stg)                                                           \
    {                                                                          \
        uint8_t* sBhi = smem + (stg)*STAGE_BYTES + S_BHI;                      \
        uint8_t* sBlo = smem + (stg)*STAGE_BYTES + S_BLO;                      \
        uint32_t hh[8], ll[8];                                                 \
        _Pragma("unroll")                                                      \
        for (int q = 0; q < 4; q++) {                                          \
            float4 v = fb[q];                                                  \
            __half2 h0 = __float22half2_rn(make_float2(v.x, v.y));             \
            __half2 h1 = __float22half2_rn(make_float2(v.z, v.w));             \
            float2 f0 = __half22float2(h0), f1 = __half22float2(h1);           \
            __half2 l0 = __float22half2_rn(make_float2(v.x-f0.x, v.y-f0.y));   \
            __half2 l1 = __float22half2_rn(make_float2(v.z-f1.x, v.w-f1.y));   \
            hh[2*q] = *(uint32_t*)&h0; hh[2*q+1] = *(uint32_t*)&h1;            \
            ll[2*q] = *(uint32_t*)&l0; ll[2*q+1] = *(uint32_t*)&l1;            \
        }                                                                      \
        *(uint4*)(sBhi + bOff0) = make_uint4(hh[0],hh[1],hh[2],hh[3]);         \
        *(uint4*)(sBhi + bOff1) = make_uint4(hh[4],hh[5],hh[6],hh[7]);         \
        *(uint4*)(sBlo + bOff0) = make_uint4(ll[0],ll[1],ll[2],ll[3]);         \
        *(uint4*)(sBlo + bOff1) = make_uint4(ll[4],ll[5],ll[6],ll[7]);         \
    }

#define COMPUTE(stg)                                                           \
    {                                                                          \
        uint32_t aB   = sbase + (stg)*STAGE_BYTES + S_A;                       \
        uint32_t bHiB = sbase + (stg)*STAGE_BYTES + S_BHI;                     \
        uint32_t bLoB = sbase + (stg)*STAGE_BYTES + S_BLO;                     \
        _Pragma("unroll")                                                      \
        for (int ks = 0; ks < 2; ks++) {                                       \
            uint32_t ah[4][4];                                                 \
            _Pragma("unroll")                                                  \
            for (int i = 0; i < 4; i++) {                                      \
                int r = wm * 64 + i * 16 + (lane & 15);                        \
                int cb = ks*32 + ((lane >> 4) << 4);                           \
                ldsm4(ah[i][0], ah[i][1], ah[i][2], ah[i][3],                  \
                      aB + (uint32_t)SWZA(r, cb));                             \
            }                                                                  \
            uint32_t bh[4][2], bl[4][2];                                       \
            _Pragma("unroll")                                                  \
            for (int jp = 0; jp < 2; jp++) {                                   \
                int r = ks * 16 + (lane & 15);                                 \
                int cb = wn * 64 + jp * 32 + ((lane >> 4) << 4);               \
                uint32_t ad = (uint32_t)SWZB(r, cb);                           \
                uint32_t r0,r1,r2,r3;                                          \
                ldsm4t(r0, r1, r2, r3, bHiB + ad);                             \
                bh[jp*2][0]=r0; bh[jp*2][1]=r1; bh[jp*2+1][0]=r2; bh[jp*2+1][1]=r3; \
                ldsm4t(r0, r1, r2, r3, bLoB + ad);                             \
                bl[jp*2][0]=r0; bl[jp*2][1]=r1; bl[jp*2+1][0]=r2; bl[jp*2+1][1]=r3; \
            }                                                                  \
            _Pragma("unroll")                                                  \
            for (int i = 0; i < 4; i++)                                        \
                _Pragma("unroll")                                              \
                for (int j = 0; j < 4; j++) {                                  \
                    mma16816(acc[i][j], ah[i], bh[j][0], bh[j][1]);            \
                    mma16816(acc[i][j], ah[i], bl[j][0], bl[j][1]);            \
                }                                                              \
        }                                                                      \
    }

    // Prologue: stage chunk 0
    ISSUE_A(0, 0);
    LOAD_B(0);
    STORE_B(0);
    CP_WAIT0();
    __syncthreads();

    int p = 0;
#define NC (DIM/32)
#pragma unroll 1
    for (int c = 0; c < NC; c++) {
        if (c + 1 < NC) {
            ISSUE_A((c+1)*32, p ^ 1);
            LOAD_B((c+1)*32);
        }
        COMPUTE(p);
        if (c + 1 < NC) {
            STORE_B(p ^ 1);
            CP_WAIT0();
            __syncthreads();
            p ^= 1;
        }
    }
#undef NC

    // Epilogue
    int colb = wn * 32 + (lane & 3) * 2;
    float2 bz[4];
#pragma unroll
    for (int j = 0; j < 4; j++)
        bz[j] = *(const float2*)(bias + e * HID + n0 + colb + j * 8);

#pragma unroll
    for (int i = 0; i < 4; i++) {
#pragma unroll
        for (int rh = 0; rh < 2; rh++) {
            int row = wm * 64 + i * 16 + rh * 8 + (lane >> 2);
            int aid = rowid[row];
            if (aid < 0) continue;
#pragma unroll
            for (int j = 0; j < 4; j++) {
                float ox = acc[i][j][rh*2+0] + bz[j].x;
                float oy = acc[i][j][rh*2+1] + bz[j].y;
                if (pass1) {
                    ox = fmaxf(ox, 0.f); oy = fmaxf(oy, 0.f);
                    __half2 h = __float22half2_rn(make_float2(ox, oy));
                    *(__half2*)(g_h16 + (size_t)aid * HID + n0 + colb + j * 8) = h;
                } else {
                    *(float2*)(g_o + (size_t)aid * DIM + n0 + colb + j * 8) = make_float2(ox, oy);
                }
            }
        }
    }
#undef ISSUE_A
#undef LOAD_B
#undef STORE_B
#undef COMPUTE
}

__device__ float block_reduce_256(float v, volatile float* red) {
    int t = threadIdx.x;
    red[t] = v; __syncthreads();
    if (t < 128) red[t] += red[t + 128]; __syncthreads();
    if (t <  64) red[t] += red[t +  64]; __syncthreads();
    if (t <  32) {
        red[t] += red[t + 32]; __syncwarp();
        red[t] += red[t + 16]; __syncwarp();
        red[t] += red[t +  8]; __syncwarp();
        red[t] += red[t +  4]; __syncwarp();
        red[t] += red[t +  2]; __syncwarp();
        red[t] += red[t +  1]; __syncwarp();
    }
    __syncthreads();
    float r = red[0];
    __syncthreads();
    return r;
}

__global__ void finalize_kernel(const float* __restrict__ ln_w,
                                const float* __restrict__ ln_b,
                                const float* __restrict__ W_los,
                                const float* __restrict__ b_los,
                                float* __restrict__ d_out) {
    __shared__ float red[256];
    int b = blockIdx.x, t = threadIdx.x;
    float v[4];
#pragma unroll
    for (int i = 0; i < 4; i++) {
        int d = t + (i << 8);
        float acc = 0.f;
        for (int m = 0; m < NM; m++) {
            int n = (b << 4) + m;
#pragma unroll
            for (int k = 0; k < 4; k++) {
                int a = (n << 2) + k;
                acc = fmaf(g_tk_gate[a], g_o[(size_t)a * DIM + d], acc);
            }
        }
        v[i] = acc;
    }
    float s = 0.f, ss = 0.f;
#pragma unroll
    for (int i = 0; i < 4; i++) { s += v[i]; ss = fmaf(v[i], v[i], ss); }
    float sum   = block_reduce_256(s,  red);
    float sumsq = block_reduce_256(ss, red);
    float mu   = sum * (1.f / 1024.f);
    float var  = sumsq * (1.f / 1024.f) - mu * mu;
    float rstd = 1.f / sqrtf(var + 1e-5f);

    float sc[10];
#pragma unroll
    for (int o = 0; o < 10; o++) sc[o] = 0.f;
#pragma unroll
    for (int i = 0; i < 4; i++) {
        int d = t + (i << 8);
        float f = (v[i] - mu) * rstd * ln_w[d] + ln_b[d];
        const float* wl = W_los + (size_t)d * NOUT;
#pragma unroll
        for (int o = 0; o < 10; o++) sc[o] = fmaf(f, wl[o], sc[o]);
    }
    for (int o = 0; o < 10; o++) {
        float r = block_reduce_256(sc[o], red);
        if (t == 0) d_out[b * NOUT + o] = r + b_los[o];
    }
}

__global__ void predloss_kernel(const float* __restrict__ true_y, float* __restrict__ d_out) {
    __shared__ float red[256];
    int t = threadIdx.x;
    float s = 0.f;
    for (int i = t; i < NB * NOUT; i += 256) {
        float dd = d_out[i] - true_y[i];
        s = fmaf(dd, dd, s);
    }
    float r = block_reduce_256(s, red);
    if (t == 0) d_out[641] = r * (1.f / 640.f);
}

extern "C" void kernel_launch(void* const* d_in, const int* in_sizes, int n_in,
                              void* d_out, int out_size) {
    const float* x      = (const float*)d_in[0];
    const float* wg     = (const float*)d_in[1];
    const float* W1     = (const float*)d_in[2];
    const float* b1     = (const float*)d_in[3];
    const float* W2     = (const float*)d_in[4];
    const float* b2     = (const float*)d_in[5];
    const float* ln_w   = (const float*)d_in[6];
    const float* ln_b   = (const float*)d_in[7];
    const float* W_los  = (const float*)d_in[8];
    const float* b_los  = (const float*)d_in[9];
    const float* true_y = (const float*)d_in[10];
    float* out = (float*)d_out;

    static int smem_set = 0;
    if (!smem_set) {
        cudaFuncSetAttribute(expert_gemm_mma,
                             cudaFuncAttributeMaxDynamicSharedMemorySize, SMEM_TOTAL);
        smem_set = 1;
    }

    init_kernel<<<1, 32>>>();
    gate_kernel<<<NTOK, 256>>>(x, wg);
    loss_part_kernel<<<16, 256>>>();
    loss_final_kernel<<<1, 32>>>(out);
    expert_gemm_mma<<<dim3(8, 8, 16), 256, SMEM_TOTAL>>>(W1, b1, 1);
    expert_gemm_mma<<<dim3(8, 8, 16), 256, SMEM_TOTAL>>>(W2, b2, 0);
    finalize_kernel<<<64, 256>>>(ln_w, ln_b, W_los, b_los, out);
    predloss_kernel<<<1, 256>>>(true_y, out);
}